// round 8
// baseline (speedup 1.0000x reference)
#include <cuda_runtime.h>
#include <cuda_bf16.h>
#include <cstdint>
#include <math.h>

// ---------------- problem dims ----------------
#define B    64
#define PL   128
#define RL   64
#define TDEC 63
#define NT   50
#define NP   20
#define TE   100
#define HID  100
#define GH   512
#define G3   1536
#define G4   2048
#define DE   300
#define VW   32000
#define KE   500
#define KD   1612
#define KC   1524
#define NEGV -1000000000.0f

// ---- bf16-split vocab GEMM dims ----
#define KSEG 1612
#define KP   4864
#define MP   4096
#define SSTRIDE 40
#define VTM  256
#define VTN  128
#define VSTAGE_A (256*SSTRIDE*2)
#define VSTAGE_B (128*SSTRIDE*2)
#define VSTAGE   (VSTAGE_A + VSTAGE_B)
#define VSMEM    (3*VSTAGE)

// ---------------- scratch ----------------
constexpr size_t SZ_TEF = (size_t)B*NT*NP*300;
constexpr size_t SZ_SL  = (size_t)B*NT*NP;
constexpr size_t SZ_SG  = (size_t)B*NT*200;
constexpr size_t SZ_UBG = (size_t)B*NT*100;
constexpr size_t SZ_PIN = (size_t)B*PL*KE;
constexpr size_t SZ_GXE = (size_t)B*PL*G3;
constexpr size_t SZ_PO  = (size_t)B*PL*GH;
constexpr size_t SZ_H   = (size_t)B*GH;
constexpr size_t SZ_RV  = (size_t)TDEC*B*600;
constexpr size_t SZ_Z   = (size_t)TDEC*B*KD;
constexpr size_t SZ_DIN2= (size_t)B*KC;
constexpr size_t SZ_CP  = (size_t)8*B*G4;
constexpr size_t SZ_GXRV= (size_t)TDEC*B*G3;
constexpr size_t SZ_WCB = (size_t)G4*KC;
constexpr size_t SZ_WRV = (size_t)G3*600;
constexpr size_t SZ_WENC= (size_t)G3*GH;

constexpr size_t OFF_TEF = 0;
constexpr size_t OFF_SL  = OFF_TEF + SZ_TEF;
constexpr size_t OFF_SG  = OFF_SL  + SZ_SL;
constexpr size_t OFF_UBG = OFF_SG  + SZ_SG;
constexpr size_t OFF_PIN = OFF_UBG + SZ_UBG;
constexpr size_t OFF_GXE = OFF_PIN + SZ_PIN;
constexpr size_t OFF_PO  = OFF_GXE + SZ_GXE;
constexpr size_t OFF_HA  = OFF_PO  + SZ_PO;
constexpr size_t OFF_HB  = OFF_HA  + SZ_H;
constexpr size_t OFF_RV  = OFF_HB  + SZ_H;
constexpr size_t OFF_Z   = OFF_RV  + SZ_RV;
constexpr size_t OFF_DIN2= OFF_Z   + SZ_Z;
constexpr size_t OFF_CP  = OFF_DIN2+ SZ_DIN2;
constexpr size_t OFF_GXRV= OFF_CP  + SZ_CP;
constexpr size_t OFF_WCB = OFF_GXRV+ SZ_GXRV;
constexpr size_t OFF_WRV = OFF_WCB + SZ_WCB;
constexpr size_t OFF_WENC= OFF_WRV + SZ_WRV;
constexpr size_t SZ_TOTAL = OFF_WENC + SZ_WENC;

__device__ float g_buf[SZ_TOTAL];
__device__ __align__(16) __nv_bfloat16 g_Ws[(size_t)VW * KP];
__device__ __align__(16) __nv_bfloat16 g_As[(size_t)MP * KP];

__device__ __forceinline__ float sigmoidf_(float x) { return 1.0f / (1.0f + expf(-x)); }
__device__ __forceinline__ uint32_t smem_u32(const void* p) {
    uint32_t a;
    asm("{ .reg .u64 t; cvta.to.shared.u64 t, %1; cvt.u32.u64 %0, t; }" : "=r"(a) : "l"(p));
    return a;
}

// ---------------- small utility kernels ----------------
__global__ void k_zero(float* p, size_t n) {
    size_t i = (size_t)blockIdx.x*blockDim.x + threadIdx.x;
    if (i < n) p[i] = 0.f;
}

__global__ void k_gather_tef(const float* __restrict__ te, const int* __restrict__ triple,
                             float* __restrict__ tef) {
    size_t i = (size_t)blockIdx.x*blockDim.x + threadIdx.x;
    size_t total = (size_t)B*NT*NP*3*25;
    if (i >= total) return;
    size_t ent = i / 25; int off = (int)(i % 25) * 4;
    size_t tri = ent / 3; int e = (int)(ent % 3);
    int idx = triple[ent];
    float4 v = *reinterpret_cast<const float4*>(te + (size_t)idx*TE + off);
    *reinterpret_cast<float4*>(tef + tri*300 + e*100 + off) = v;
}

__global__ void k_gather_rv(const float* __restrict__ we, const float* __restrict__ te,
                            const int* __restrict__ resp, const int* __restrict__ rtrip,
                            float* __restrict__ rv, float* __restrict__ Z) {
    size_t i = (size_t)blockIdx.x*blockDim.x + threadIdx.x;
    size_t total = (size_t)TDEC*B*150;
    if (i >= total) return;
    size_t tb = i / 150; int f = (int)(i % 150);
    int t = (int)(tb / B), b = (int)(tb % B);
    float4 v;
    if (f < 75) {
        int w = resp[b*RL + t];
        v = *reinterpret_cast<const float4*>(we + (size_t)w*DE + f*4);
    } else {
        int f2 = f - 75; int e = f2 / 25; int off = (f2 % 25) * 4;
        int idx = rtrip[((size_t)b*RL + t)*3 + e];
        v = *reinterpret_cast<const float4*>(te + (size_t)idx*TE + off);
    }
    *reinterpret_cast<float4*>(rv + tb*600 + f*4) = v;
    *reinterpret_cast<float4*>(Z + tb*KD + 1012 + f*4) = v;
}

__global__ void k_triple_score(const float* __restrict__ tef, const int* __restrict__ triple,
                               const float* __restrict__ wh_w, const float* __restrict__ wh_b,
                               const float* __restrict__ wr_w, const float* __restrict__ wr_b,
                               const float* __restrict__ wt_w, const float* __restrict__ wt_b,
                               float* __restrict__ sl) {
    int g = blockIdx.x;
    const float* tb = tef + (size_t)g*300;
    __shared__ float e[300];
    __shared__ float red[128];
    int tid = threadIdx.x;
    for (int i = tid; i < 300; i += 128) e[i] = tb[i];
    __syncthreads();
    float contrib = 0.f;
    if (tid < HID) {
        int j = tid;
        float a = wh_b[j] + wt_b[j];
        float r = wr_b[j];
        const float* whr = wh_w + (size_t)j*TE;
        const float* wtr = wt_w + (size_t)j*TE;
        const float* wrr = wr_w + (size_t)j*TE;
        #pragma unroll 4
        for (int k = 0; k < TE; k++) {
            a += e[k]*whr[k] + e[200+k]*wtr[k];
            r += e[100+k]*wrr[k];
        }
        contrib = r * tanhf(a);
    }
    red[tid] = contrib; __syncthreads();
    for (int s = 64; s; s >>= 1) { if (tid < s) red[tid] += red[tid+s]; __syncthreads(); }
    if (tid == 0)
        sl[g] = (triple[(size_t)g*3] == 0) ? NEGV : red[0];
}

__global__ void k_graph_softmax(const float* __restrict__ sl, const float* __restrict__ tef,
                                float* __restrict__ sg) {
    int g = blockIdx.x;
    int tid = threadIdx.x;
    __shared__ float sa[NP];
    if (tid == 0) {
        float m = -1e30f;
        for (int p = 0; p < NP; p++) m = fmaxf(m, sl[(size_t)g*NP + p]);
        float sum = 0.f;
        for (int p = 0; p < NP; p++) { float ev = expf(sl[(size_t)g*NP + p] - m); sa[p] = ev; sum += ev; }
        float inv = 1.f / sum;
        for (int p = 0; p < NP; p++) sa[p] *= inv;
    }
    __syncthreads();
    const float* tb = tef + (size_t)g*NP*300;
    for (int d = tid; d < 200; d += 64) {
        int dd = (d < 100) ? d : d + 100;
        float s = 0.f;
        #pragma unroll
        for (int p = 0; p < NP; p++) s += sa[p]*tb[(size_t)p*300 + dd];
        sg[(size_t)g*200 + d] = s;
    }
}

__global__ void k_ubg(const float* __restrict__ sg, const float* __restrict__ ub_w,
                      const float* __restrict__ ub_b, float* __restrict__ ubg) {
    int g = blockIdx.x;
    int tid = threadIdx.x;
    __shared__ float s[200];
    for (int i = tid; i < 200; i += 128) s[i] = sg[(size_t)g*200 + i];
    __syncthreads();
    if (tid < HID) {
        float acc = ub_b[tid];
        const float* w = ub_w + (size_t)tid*200;
        #pragma unroll 4
        for (int k = 0; k < 200; k++) acc += s[k]*w[k];
        ubg[(size_t)g*HID + tid] = acc;
    }
}

__global__ void k_post_in(const float* __restrict__ we, const float* __restrict__ sg,
                          const int* __restrict__ post, const int* __restrict__ ptrip,
                          float* __restrict__ pin) {
    size_t i = (size_t)blockIdx.x*blockDim.x + threadIdx.x;
    size_t total = (size_t)B*PL*125;
    if (i >= total) return;
    size_t bt = i / 125; int f = (int)(i % 125);
    float4 v;
    if (f < 75) {
        v = *reinterpret_cast<const float4*>(we + (size_t)post[bt]*DE + f*4);
    } else {
        int b = (int)(bt / PL);
        int n = ptrip[bt];
        v = *reinterpret_cast<const float4*>(sg + ((size_t)b*NT + n)*200 + (f-75)*4);
    }
    *reinterpret_cast<float4*>(pin + bt*KE + f*4) = v;
}

// build W_comb [G4 x KC]
__global__ void k_build_wcomb(const float* __restrict__ Wih, const float* __restrict__ Whh,
                              float* __restrict__ Wc) {
    size_t i = (size_t)blockIdx.x*blockDim.x + threadIdx.x;
    if (i >= (size_t)G4*KC) return;
    int c = (int)(i % KC);
    int r = (int)(i / KC);
    float v = 0.f;
    if (r < 1024) {
        v = (c < 1012) ? Wih[(size_t)r*KD + c] : Whh[(size_t)r*GH + (c - 1012)];
    } else if (r < 1536) {
        if (c < 1012) v = Wih[(size_t)r*KD + c];
    } else {
        if (c >= 1012) v = Whh[(size_t)(r - 512)*GH + (c - 1012)];
    }
    Wc[i] = v;
}

__global__ void k_build_wrv(const float* __restrict__ Wih, float* __restrict__ Wrv) {
    size_t i = (size_t)blockIdx.x*blockDim.x + threadIdx.x;
    if (i >= (size_t)G3*600) return;
    int c = (int)(i % 600);
    int r = (int)(i / 600);
    Wrv[i] = Wih[(size_t)r*KD + 1012 + c];
}

// interleave Whh_e into 8 blocks of 192 rows: block g row (gate*64+jl) = Whh[gate*512 + g*64 + jl]
__global__ void k_build_wenc(const float* __restrict__ Whh, float* __restrict__ We) {
    size_t i = (size_t)blockIdx.x*blockDim.x + threadIdx.x;
    if (i >= (size_t)G3*GH) return;
    int k = (int)(i % GH);
    int rp = (int)(i / GH);
    int g = rp / 192, l = rp % 192;
    int gate = l / 64, jl = l % 64;
    We[i] = Whh[(size_t)(gate*GH + g*64 + jl)*GH + k];
}

__global__ void k_h2din2(const float* __restrict__ h, float* __restrict__ din2) {
    int i = blockIdx.x*blockDim.x + threadIdx.x;
    if (i >= B*GH) return;
    int b = i / GH, j = i % GH;
    din2[(size_t)b*KC + 1012 + j] = h[i];
}

// ---------------- fp32 tiled GEMMs ----------------
__global__ void gemm_bias(const float* __restrict__ A, const float* __restrict__ W,
                          const float* __restrict__ bias, float* __restrict__ C,
                          int M, int N, int K) {
    __shared__ float As[16][64];
    __shared__ float Ws[16][64];
    int bm = blockIdx.x * 64, bn = blockIdx.y * 64;
    int tid = threadIdx.x;
    int tx = tid & 15, ty = tid >> 4;
    float acc[4][4] = {};
    int r  = tid >> 2;
    int kk = (tid & 3) * 4;
    for (int k0 = 0; k0 < K; k0 += 16) {
        int gk = k0 + kk;
        float4 va = make_float4(0,0,0,0);
        int gm = bm + r;
        if (gm < M) {
            if (gk + 3 < K) va = *reinterpret_cast<const float4*>(A + (size_t)gm*K + gk);
            else { float t0=0,t1=0,t2=0,t3=0;
                   if (gk+0<K) t0=A[(size_t)gm*K+gk+0]; if (gk+1<K) t1=A[(size_t)gm*K+gk+1];
                   if (gk+2<K) t2=A[(size_t)gm*K+gk+2]; if (gk+3<K) t3=A[(size_t)gm*K+gk+3];
                   va = make_float4(t0,t1,t2,t3); }
        }
        As[kk+0][r]=va.x; As[kk+1][r]=va.y; As[kk+2][r]=va.z; As[kk+3][r]=va.w;
        float4 vw = make_float4(0,0,0,0);
        int gn = bn + r;
        if (gn < N) {
            if (gk + 3 < K) vw = *reinterpret_cast<const float4*>(W + (size_t)gn*K + gk);
            else { float t0=0,t1=0,t2=0,t3=0;
                   if (gk+0<K) t0=W[(size_t)gn*K+gk+0]; if (gk+1<K) t1=W[(size_t)gn*K+gk+1];
                   if (gk+2<K) t2=W[(size_t)gn*K+gk+2]; if (gk+3<K) t3=W[(size_t)gn*K+gk+3];
                   vw = make_float4(t0,t1,t2,t3); }
        }
        Ws[kk+0][r]=vw.x; Ws[kk+1][r]=vw.y; Ws[kk+2][r]=vw.z; Ws[kk+3][r]=vw.w;
        __syncthreads();
        #pragma unroll
        for (int k = 0; k < 16; k++) {
            float4 a = *reinterpret_cast<const float4*>(&As[k][ty*4]);
            float4 b = *reinterpret_cast<const float4*>(&Ws[k][tx*4]);
            acc[0][0]+=a.x*b.x; acc[0][1]+=a.x*b.y; acc[0][2]+=a.x*b.z; acc[0][3]+=a.x*b.w;
            acc[1][0]+=a.y*b.x; acc[1][1]+=a.y*b.y; acc[1][2]+=a.y*b.z; acc[1][3]+=a.y*b.w;
            acc[2][0]+=a.z*b.x; acc[2][1]+=a.z*b.y; acc[2][2]+=a.z*b.z; acc[2][3]+=a.z*b.w;
            acc[3][0]+=a.w*b.x; acc[3][1]+=a.w*b.y; acc[3][2]+=a.w*b.z; acc[3][3]+=a.w*b.w;
        }
        __syncthreads();
    }
    #pragma unroll
    for (int i = 0; i < 4; i++) {
        int gm = bm + ty*4 + i; if (gm >= M) continue;
        #pragma unroll
        for (int j = 0; j < 4; j++) {
            int gn = bn + tx*4 + j; if (gn >= N) continue;
            C[(size_t)gm*N + gn] = acc[i][j] + (bias ? bias[gn] : 0.f);
        }
    }
}

__global__ void gemm_splitk(const float* __restrict__ A, const float* __restrict__ W,
                            float* __restrict__ Cp, int M, int N, int K, int kchunk) {
    __shared__ float As[16][64];
    __shared__ float Ws[16][64];
    int z = blockIdx.y;
    int ks = z * kchunk;
    int ke = min(K, ks + kchunk);
    int bn = blockIdx.x * 64;
    int tid = threadIdx.x;
    int tx = tid & 15, ty = tid >> 4;
    float acc[4][4] = {};
    int r  = tid >> 2;
    int kk = (tid & 3) * 4;
    for (int k0 = ks; k0 < ke; k0 += 16) {
        int gk = k0 + kk;
        float4 va = make_float4(0,0,0,0);
        if (r < M) {
            if (gk + 3 < ke) va = *reinterpret_cast<const float4*>(A + (size_t)r*K + gk);
            else { float t0=0,t1=0,t2=0,t3=0;
                   if (gk+0<ke) t0=A[(size_t)r*K+gk+0]; if (gk+1<ke) t1=A[(size_t)r*K+gk+1];
                   if (gk+2<ke) t2=A[(size_t)r*K+gk+2]; if (gk+3<ke) t3=A[(size_t)r*K+gk+3];
                   va = make_float4(t0,t1,t2,t3); }
        }
        As[kk+0][r]=va.x; As[kk+1][r]=va.y; As[kk+2][r]=va.z; As[kk+3][r]=va.w;
        float4 vw = make_float4(0,0,0,0);
        int gn = bn + r;
        if (gn < N) {
            if (gk + 3 < ke) vw = *reinterpret_cast<const float4*>(W + (size_t)gn*K + gk);
            else { float t0=0,t1=0,t2=0,t3=0;
                   if (gk+0<ke) t0=W[(size_t)gn*K+gk+0]; if (gk+1<ke) t1=W[(size_t)gn*K+gk+1];
                   if (gk+2<ke) t2=W[(size_t)gn*K+gk+2]; if (gk+3<ke) t3=W[(size_t)gn*K+gk+3];
                   vw = make_float4(t0,t1,t2,t3); }
        }
        Ws[kk+0][r]=vw.x; Ws[kk+1][r]=vw.y; Ws[kk+2][r]=vw.z; Ws[kk+3][r]=vw.w;
        __syncthreads();
        #pragma unroll
        for (int k = 0; k < 16; k++) {
            float4 a = *reinterpret_cast<const float4*>(&As[k][ty*4]);
            float4 b = *reinterpret_cast<const float4*>(&Ws[k][tx*4]);
            acc[0][0]+=a.x*b.x; acc[0][1]+=a.x*b.y; acc[0][2]+=a.x*b.z; acc[0][3]+=a.x*b.w;
            acc[1][0]+=a.y*b.x; acc[1][1]+=a.y*b.y; acc[1][2]+=a.y*b.z; acc[1][3]+=a.y*b.w;
            acc[2][0]+=a.z*b.x; acc[2][1]+=a.z*b.y; acc[2][2]+=a.z*b.z; acc[2][3]+=a.z*b.w;
            acc[3][0]+=a.w*b.x; acc[3][1]+=a.w*b.y; acc[3][2]+=a.w*b.z; acc[3][3]+=a.w*b.w;
        }
        __syncthreads();
    }
    float* Cz = Cp + (size_t)z*M*N;
    #pragma unroll
    for (int i = 0; i < 4; i++) {
        int gm = ty*4 + i; if (gm >= M) continue;
        #pragma unroll
        for (int j = 0; j < 4; j++) {
            int gn = bn + tx*4 + j; if (gn >= N) continue;
            Cz[(size_t)gm*N + gn] = acc[i][j];
        }
    }
}

// ---------------- fused encoder step: gh GEMM + GRU gates, one launch --------------
// grid 8 CTAs (j-groups of 64), 512 threads; Wenc interleaved [8][192][512]
__global__ void __launch_bounds__(512) enc_step(
        const float* __restrict__ h_in, const float* __restrict__ Wenc,
        const float* __restrict__ gxe, const float* __restrict__ bhh,
        float* __restrict__ h_out, float* __restrict__ po,
        const int* __restrict__ post_length, int t) {
    extern __shared__ float sm[];
    float* As  = sm;                    // [16][64]
    float* Wsh = sm + 16*64;            // [16][192]
    float* Cs  = sm + 16*64 + 16*192;   // [64][192]
    int g = blockIdx.x;
    int tid = threadIdx.x;
    int warp = tid >> 5, lane = tid & 31;
    float acc[4][6] = {};
    const float* Wg = Wenc + (size_t)g*192*GH;
    for (int k0 = 0; k0 < GH; k0 += 16) {
        {
            int b = tid >> 3, kk = (tid & 7) * 2;
            float2 v = *reinterpret_cast<const float2*>(h_in + (size_t)b*GH + k0 + kk);
            As[kk*64 + b] = v.x; As[(kk+1)*64 + b] = v.y;
        }
        #pragma unroll
        for (int i = 0; i < 6; i++) {
            int idx = i*512 + tid;
            int r = idx >> 4, kk = idx & 15;
            Wsh[kk*192 + r] = Wg[(size_t)r*GH + k0 + kk];
        }
        __syncthreads();
        #pragma unroll
        for (int kk = 0; kk < 16; kk++) {
            float a[4], w[6];
            #pragma unroll
            for (int i = 0; i < 4; i++) a[i] = As[kk*64 + warp*4 + i];
            #pragma unroll
            for (int j = 0; j < 6; j++) w[j] = Wsh[kk*192 + lane*6 + j];
            #pragma unroll
            for (int i = 0; i < 4; i++)
            #pragma unroll
            for (int j = 0; j < 6; j++) acc[i][j] += a[i]*w[j];
        }
        __syncthreads();
    }
    #pragma unroll
    for (int i = 0; i < 4; i++)
    #pragma unroll
    for (int j = 0; j < 6; j++)
        Cs[(warp*4 + i)*192 + lane*6 + j] = acc[i][j];
    __syncthreads();
    #pragma unroll
    for (int it = 0; it < 8; it++) {
        int idx = it*512 + tid;          // 0..4095
        int b = idx >> 6, jl = idx & 63;
        int j = g*64 + jl;
        float ghr = Cs[b*192 + jl]        + bhh[j];
        float ghz = Cs[b*192 + 64 + jl]   + bhh[GH + j];
        float ghn = Cs[b*192 + 128 + jl]  + bhh[2*GH + j];
        const float* gx = gxe + ((size_t)b*PL + t)*G3;
        float r = sigmoidf_(gx[j] + ghr);
        float z = sigmoidf_(gx[GH+j] + ghz);
        float n = tanhf(gx[2*GH+j] + r*ghn);
        float hold = h_in[(size_t)b*GH + j];
        float hn = (1.f - z)*n + z*hold;
        bool valid = t < post_length[b];
        h_out[(size_t)b*GH + j] = valid ? hn : hold;
        po[((size_t)b*PL + t)*GH + j] = valid ? hn : 0.f;
    }
}

// ---------------- fused decoder step (prev gates + attn + q + da + tv) -------------
__global__ void __launch_bounds__(256) dec_fused(
        float* __restrict__ din2, const float* __restrict__ po,
        const float* __restrict__ cp, const float* __restrict__ gxrv_prev,
        const float* __restrict__ bhh,
        const float* __restrict__ wb_w, const float* __restrict__ wb_b,
        const float* __restrict__ wc_w, const float* __restrict__ wc_b,
        const float* __restrict__ vb_w, const float* __restrict__ vb_b,
        const float* __restrict__ ubg, const float* __restrict__ sg,
        const float* __restrict__ tef, float* __restrict__ Z,
        int t, int do_gates) {
    int b = blockIdx.x, tid = threadIdx.x;
    int lane = tid & 31, wid = tid >> 5;
    __shared__ float hs[GH];
    __shared__ float sc2[256];
    __shared__ float al[PL];
    __shared__ float wbh[HID];
    __shared__ float das[NT];
    __shared__ float qs[300];
    __shared__ float sw[NT*NP];
    // phase A: apply gates of step t-1
    if (do_gates) {
        #pragma unroll
        for (int jj = 0; jj < 2; jj++) {
            int j = jj*256 + tid;
            float cr = 0.f, cz = 0.f, cxn = 0.f, chn = 0.f;
            #pragma unroll
            for (int z = 0; z < 8; z++) {
                const float* p = cp + ((size_t)z*B + b)*G4;
                cr += p[j]; cz += p[512+j]; cxn += p[1024+j]; chn += p[1536+j];
            }
            const float* gr = gxrv_prev + (size_t)b*G3;
            float r  = sigmoidf_(cr + gr[j] + bhh[j]);
            float zz = sigmoidf_(cz + gr[GH+j] + bhh[GH+j]);
            float n  = tanhf(cxn + gr[2*GH+j] + r*(chn + bhh[2*GH+j]));
            float hold = din2[(size_t)b*KC + 1012 + j];
            float hn = (1.f - zz)*n + zz*hold;
            din2[(size_t)b*KC + 1012 + j] = hn;
            Z[((size_t)(t-1)*B + b)*KD + j] = hn;
        }
        __syncthreads();
    }
    // phase B: load h
    for (int i = tid; i < GH; i += 256) hs[i] = din2[(size_t)b*KC + 1012 + i];
    __syncthreads();
    // phase C: attention scores + q/wbh
    {
        int p = tid >> 1, hf = tid & 1;
        const float* row = po + ((size_t)b*PL + p)*GH + hf*256;
        const float* h2 = hs + hf*256;
        float s = 0.f;
        for (int k = 0; k < 256; k += 4) {
            float4 v = *reinterpret_cast<const float4*>(row + k);
            s += v.x*h2[k] + v.y*h2[k+1] + v.z*h2[k+2] + v.w*h2[k+3];
        }
        sc2[tid] = s;
    }
    for (int j = tid; j < 400; j += 256) {
        const float* w;
        float acc;
        if (j < 300) { acc = wc_b[j]; w = wc_w + (size_t)j*GH; }
        else         { acc = wb_b[j-300]; w = wb_w + (size_t)(j-300)*GH; }
        for (int k = 0; k < GH; k += 4) {
            float4 v = *reinterpret_cast<const float4*>(w + k);
            acc += v.x*hs[k] + v.y*hs[k+1] + v.z*hs[k+2] + v.w*hs[k+3];
        }
        if (j < 300) qs[j] = acc;
        else wbh[j-300] = acc;
    }
    __syncthreads();
    // phase D: attn softmax (warp0) + dls (tid<50)
    __shared__ float dls[NT];
    if (wid == 0) {
        float v0 = sc2[2*lane] + sc2[2*lane+1];
        float v1 = sc2[2*(lane+32)] + sc2[2*(lane+32)+1];
        float v2 = sc2[2*(lane+64)] + sc2[2*(lane+64)+1];
        float v3 = sc2[2*(lane+96)] + sc2[2*(lane+96)+1];
        float m = fmaxf(fmaxf(v0, v1), fmaxf(v2, v3));
        for (int o = 16; o; o >>= 1) m = fmaxf(m, __shfl_xor_sync(0xffffffffu, m, o));
        float e0 = expf(v0-m), e1 = expf(v1-m), e2 = expf(v2-m), e3 = expf(v3-m);
        float s = e0+e1+e2+e3;
        for (int o = 16; o; o >>= 1) s += __shfl_xor_sync(0xffffffffu, s, o);
        float inv = 1.f/s;
        al[lane] = e0*inv; al[lane+32] = e1*inv; al[lane+64] = e2*inv; al[lane+96] = e3*inv;
    } else if (tid >= 32 && tid < 32 + NT) {
        int n = tid - 32;
        float s = 0.f;
        const float* u = ubg + ((size_t)b*NT + n)*HID;
        for (int j = 0; j < HID; j++) s += vb_w[j]*tanhf(wbh[j] + u[j]);
        dls[n] = s + vb_b[0];
    }
    __syncthreads();
    // phase E: cv + da softmax
    for (int d = tid; d < GH; d += 256) {
        float acc = 0.f;
        for (int p = 0; p < PL; p++) acc += al[p]*po[((size_t)b*PL + p)*GH + d];
        din2[(size_t)b*KC + d] = acc;
    }
    if (wid == 0) {
        float a0 = (lane < NT) ? dls[lane] : -1e30f;
        float a1 = (lane+32 < NT) ? dls[lane+32] : -1e30f;
        float m = fmaxf(a0, a1);
        for (int o = 16; o; o >>= 1) m = fmaxf(m, __shfl_xor_sync(0xffffffffu, m, o));
        float e0 = (lane < NT) ? expf(a0-m) : 0.f;
        float e1 = (lane+32 < NT) ? expf(a1-m) : 0.f;
        float s = e0 + e1;
        for (int o = 16; o; o >>= 1) s += __shfl_xor_sync(0xffffffffu, s, o);
        float inv = 1.f/s;
        if (lane < NT)    das[lane] = e0*inv;
        if (lane+32 < NT) das[lane+32] = e1*inv;
    }
    __syncthreads();
    // phase F: dg + triple scores
    float* zrow = Z + ((size_t)t*B + b)*KD;
    if (tid < 200) {
        float s = 0.f;
        for (int n = 0; n < NT; n++) s += das[n]*sg[((size_t)b*NT + n)*200 + tid];
        din2[(size_t)b*KC + 512 + tid] = s;
        zrow[512 + tid] = s;
    }
    const float* tefb = tef + (size_t)b*NT*NP*300;
    for (int it = 0; it < 125; it++) {
        int pair = wid + 8*it;               // 0..999
        const float* row = tefb + (size_t)pair*300;
        float s = 0.f;
        for (int k = lane; k < 300; k += 32) s += row[k]*qs[k];
        #pragma unroll
        for (int o = 16; o; o >>= 1) s += __shfl_down_sync(0xffffffffu, s, o);
        if (lane == 0) sw[pair] = s;
    }
    __syncthreads();
    // phase G: per-n softmax * das
    for (int n = wid; n < NT; n += 8) {
        float v = (lane < NP) ? sw[n*NP + lane] : -1e30f;
        float m = v;
        for (int o = 16; o; o >>= 1) m = fmaxf(m, __shfl_xor_sync(0xffffffffu, m, o));
        float e = (lane < NP) ? expf(v - m) : 0.f;
        float su = e;
        for (int o = 16; o; o >>= 1) su += __shfl_xor_sync(0xffffffffu, su, o);
        if (lane < NP) sw[n*NP + lane] = e * das[n] / su;
    }
    __syncthreads();
    // phase H: tv accumulation
    for (int d = tid; d < 300; d += 256) {
        float acc = 0.f;
        for (int r = 0; r < NT*NP; r++) acc += sw[r]*tefb[(size_t)r*300 + d];
        din2[(size_t)b*KC + 712 + d] = acc;
        zrow[712 + d] = acc;
    }
}

// final gates for last decoder step
__global__ void dec_gates2(const float* __restrict__ cp, const float* __restrict__ gxrv_t,
                           const float* __restrict__ bhh, float* __restrict__ din2,
                           float* __restrict__ Z, int t) {
    int idx = blockIdx.x*blockDim.x + threadIdx.x;
    if (idx >= B*GH) return;
    int b = idx / GH, j = idx % GH;
    float cr = 0.f, cz = 0.f, cxn = 0.f, chn = 0.f;
    #pragma unroll
    for (int z = 0; z < 8; z++) {
        const float* p = cp + ((size_t)z*B + b)*G4;
        cr += p[j]; cz += p[512+j]; cxn += p[1024+j]; chn += p[1536+j];
    }
    const float* gr = gxrv_t + (size_t)b*G3;
    float r  = sigmoidf_(cr + gr[j] + bhh[j]);
    float zz = sigmoidf_(cz + gr[GH+j] + bhh[GH+j]);
    float n  = tanhf(cxn + gr[2*GH+j] + r*(chn + bhh[2*GH+j]));
    float hold = din2[(size_t)b*KC + 1012 + j];
    float hn = (1.f - zz)*n + zz*hold;
    din2[(size_t)b*KC + 1012 + j] = hn;
    Z[((size_t)t*B + b)*KD + j] = hn;
}

// ---------------- bf16 split prep ----------------
__global__ void k_split_W(const float* __restrict__ W, __nv_bfloat16* __restrict__ Ws) {
    size_t i = (size_t)blockIdx.x*blockDim.x + threadIdx.x;
    size_t total = (size_t)VW*(KP/8);
    if (i >= total) return;
    int cg = (int)(i % (KP/8));
    size_t r = i / (KP/8);
    int c0 = cg*8;
    __nv_bfloat16 o[8];
    #pragma unroll
    for (int e = 0; e < 8; e++) {
        int c = c0 + e;
        __nv_bfloat16 v = __float2bfloat16(0.f);
        if (c < 2*KSEG) {
            int kc = (c < KSEG) ? c : c - KSEG;
            v = __float2bfloat16(W[r*KSEG + kc]);
        } else if (c < 3*KSEG) {
            float w = W[r*KSEG + c - 2*KSEG];
            __nv_bfloat16 hh = __float2bfloat16(w);
            v = __float2bfloat16(w - __bfloat162float(hh));
        }
        o[e] = v;
    }
    *reinterpret_cast<uint4*>(Ws + r*KP + c0) = *reinterpret_cast<uint4*>(o);
}

__global__ void k_split_Z(const float* __restrict__ Z, __nv_bfloat16* __restrict__ As_) {
    size_t i = (size_t)blockIdx.x*blockDim.x + threadIdx.x;
    size_t total = (size_t)MP*(KP/8);
    if (i >= total) return;
    int cg = (int)(i % (KP/8));
    int m = (int)(i / (KP/8));
    int b = m / TDEC, t = m - b*TDEC;
    int c0 = cg*8;
    __nv_bfloat16 o[8];
    #pragma unroll
    for (int e = 0; e < 8; e++) {
        int c = c0 + e;
        __nv_bfloat16 v = __float2bfloat16(0.f);
        if (b < B && c < 3*KSEG) {
            int kc = (c < KSEG) ? c : (c < 2*KSEG ? c - KSEG : c - 2*KSEG);
            float z = Z[((size_t)t*B + b)*KD + kc];
            __nv_bfloat16 hh = __float2bfloat16(z);
            if (c >= KSEG && c < 2*KSEG) v = __float2bfloat16(z - __bfloat162float(hh));
            else v = hh;
        }
        o[e] = v;
    }
    *reinterpret_cast<uint4*>(As_ + (size_t)m*KP + c0) = *reinterpret_cast<uint4*>(o);
}

// ---------------- mma.sync bf16 vocab GEMM: 256x128 CTA tile, 3-stage ----------------
__global__ void __launch_bounds__(256) vocab_mma(
        const __nv_bfloat16* __restrict__ Ag, const __nv_bfloat16* __restrict__ Wg,
        const float* __restrict__ bout, float* __restrict__ out) {
    extern __shared__ __align__(16) char sraw[];
    const int tid = threadIdx.x;
    const int wid = tid >> 5, lane = tid & 31;
    const int m0 = blockIdx.x * VTM, n0 = blockIdx.y * VTN;
    const int wm = (wid >> 1) * 64, wn = (wid & 1) * 64;
    const int g = lane >> 2, tg = lane & 3;
    const uint32_t sb = smem_u32(sraw);

    float acc[4][8][4];
    #pragma unroll
    for (int i = 0; i < 4; i++)
    #pragma unroll
    for (int j = 0; j < 8; j++) { acc[i][j][0]=0.f; acc[i][j][1]=0.f; acc[i][j][2]=0.f; acc[i][j][3]=0.f; }

    auto load_stage = [&](int s, int k0) {
        uint32_t base = sb + (uint32_t)s*VSTAGE;
        #pragma unroll
        for (int i = 0; i < 6; i++) {
            int c = i*256 + tid;
            int isB = (c >= 1024);
            int cc = isB ? (c - 1024) : c;
            int row = cc >> 2, ch = cc & 3;
            uint32_t dst = base + (isB ? VSTAGE_A : 0u)
                         + (uint32_t)row*(SSTRIDE*2) + (uint32_t)ch*16u;
            const __nv_bfloat16* src = isB ? (Wg + (size_t)(n0+row)*KP + k0 + ch*8)
                                           : (Ag + (size_t)(m0+row)*KP + k0 + ch*8);
            asm volatile("cp.async.cg.shared.global [%0], [%1], 16;" :: "r"(dst), "l"(src));
        }
        asm volatile("cp.async.commit_group;" ::: "memory");
    };

    load_stage(0, 0); load_stage(1, 32); load_stage(2, 64);

    const int a_row = lane & 15;
    const int a_k8  = (lane >> 4) << 3;
    const int b_row = lane & 7;
    const int b_k8  = ((lane >> 3) & 1) << 3;

    const int NIT = KP/32;
    for (int kt = 0; kt < NIT; kt++) {
        if (kt + 3 < NIT) { asm volatile("cp.async.wait_group 2;" ::: "memory"); }
        else              { asm volatile("cp.async.wait_group 0;" ::: "memory"); }
        __syncthreads();
        int s = kt % 3;
        uint32_t baseA = sb + (uint32_t)s*VSTAGE;
        uint32_t baseB = baseA + VSTAGE_A;
        #pragma unroll
        for (int kk = 0; kk < 2; kk++) {
            uint32_t afr[4][4];
            #pragma unroll
            for (int mi = 0; mi < 4; mi++) {
                uint32_t ad = baseA + ((uint32_t)(wm + mi*16 + a_row)*SSTRIDE
                                       + (uint32_t)(kk*16 + a_k8))*2u;
                asm volatile("ldmatrix.sync.aligned.m8n8.x4.shared.b16 {%0,%1,%2,%3}, [%4];"
                    : "=r"(afr[mi][0]),"=r"(afr[mi][1]),"=r"(afr[mi][2]),"=r"(afr[mi][3])
                    : "r"(ad));
            }
            uint32_t bfr[8][2];
            #pragma unroll
            for (int ni = 0; ni < 8; ni++) {
                uint32_t bd = baseB + ((uint32_t)(wn + ni*8 + b_row)*SSTRIDE
                                       + (uint32_t)(kk*16 + b_k8))*2u;
                asm volatile("ldmatrix.sync.aligned.m8n8.x2.shared.b16 {%0,%1}, [%2];"
                    : "=r"(bfr[ni][0]),"=r"(bfr[ni][1]) : "r"(bd));
            }
            #pragma unroll
            for (int mi = 0; mi < 4; mi++)
            #pragma unroll
            for (int ni = 0; ni < 8; ni++) {
                asm volatile(
                  "mma.sync.aligned.m16n8k16.row.col.f32.bf16.bf16.f32 "
                  "{%0,%1,%2,%3},{%4,%5,%6,%7},{%8,%9},{%0,%1,%2,%3};"
                  : "+f"(acc[mi][ni][0]), "+f"(acc[mi][ni][1]),
                    "+f"(acc[mi][ni][2]), "+f"(acc[mi][ni][3])
                  : "r"(afr[mi][0]),"r"(afr[mi][1]),"r"(afr[mi][2]),"r"(afr[mi][3]),
                    "r"(bfr[ni][0]),"r"(bfr[ni][1]));
            }
        }
        __syncthreads();
        if (kt + 3 < NIT) load_stage(s, (kt+3)*32);
    }
    __syncthreads();

    float* Ds = (float*)sraw;
    #pragma unroll
    for (int h = 0; h < 2; h++) {
        if ((wid >> 2) == h) {
            int mbase = wm - h*128;
            #pragma unroll
            for (int mi = 0; mi < 4; mi++) {
                int mA = mbase + mi*16 + g;
                #pragma unroll
                for (int ni = 0; ni < 8; ni++) {
                    int nn = wn + ni*8 + tg*2;
                    Ds[mA*129 + nn]         = acc[mi][ni][0];
                    Ds[mA*129 + nn + 1]     = acc[mi][ni][1];
                    Ds[(mA+8)*129 + nn]     = acc[mi][ni][2];
                    Ds[(mA+8)*129 + nn + 1] = acc[mi][ni][3];
                }
            }
        }
        __syncthreads();
        for (int idx = tid; idx < VTN*128; idx += 256) {
            int n = idx >> 7, m = idx & 127;
            int mg = m0 + h*128 + m;
            if (mg < B*TDEC) {
                int bb = mg / TDEC, tt = mg - bb*TDEC;
                int ng = n0 + n;
                out[(size_t)bb*VW*TDEC + (size_t)ng*TDEC + tt] = Ds[m*129 + n] + __ldg(bout + ng);
            }
        }
        __syncthreads();
    }
}

// ---------------- launch ----------------
extern "C" void kernel_launch(void* const* d_in, const int* in_sizes, int n_in,
                              void* d_out, int out_size) {
    const float* word_emb   = (const float*)d_in[0];
    const float* transe_emb = (const float*)d_in[1];
    const float* wh_w = (const float*)d_in[2];  const float* wh_b = (const float*)d_in[3];
    const float* wr_w = (const float*)d_in[4];  const float* wr_b = (const float*)d_in[5];
    const float* wt_w = (const float*)d_in[6];  const float* wt_b = (const float*)d_in[7];
    const float* wb_w = (const float*)d_in[8];  const float* wb_b = (const float*)d_in[9];
    const float* ub_w = (const float*)d_in[10]; const float* ub_b = (const float*)d_in[11];
    const float* vb_w = (const float*)d_in[12]; const float* vb_b = (const float*)d_in[13];
    const float* wc_w = (const float*)d_in[14]; const float* wc_b = (const float*)d_in[15];
    const float* Wih_e = (const float*)d_in[16]; const float* Whh_e = (const float*)d_in[17];
    const float* bih_e = (const float*)d_in[18]; const float* bhh_e = (const float*)d_in[19];
    const float* Wih_d = (const float*)d_in[20]; const float* Whh_d = (const float*)d_in[21];
    const float* bih_d = (const float*)d_in[22]; const float* bhh_d = (const float*)d_in[23];
    const float* out_w = (const float*)d_in[24]; const float* out_b = (const float*)d_in[25];
    const int* post          = (const int*)d_in[26];
    const int* post_length   = (const int*)d_in[27];
    const int* response      = (const int*)d_in[28];
    const int* resp_triple   = (const int*)d_in[29];
    const int* post_triple   = (const int*)d_in[30];
    const int* triple        = (const int*)d_in[31];
    float* out = (float*)d_out;

    void* basep = nullptr; cudaGetSymbolAddress(&basep, g_buf);
    float* base = (float*)basep;
    void* wsp = nullptr; cudaGetSymbolAddress(&wsp, g_Ws);
    void* asp = nullptr; cudaGetSymbolAddress(&asp, g_As);
    __nv_bfloat16* Ws = (__nv_bfloat16*)wsp;
    __nv_bfloat16* As = (__nv_bfloat16*)asp;

    float* tef  = base + OFF_TEF;
    float* sl   = base + OFF_SL;
    float* sg   = base + OFF_SG;
    float* ubg  = base + OFF_UBG;
    float* pin  = base + OFF_PIN;
    float* gxe  = base + OFF_GXE;
    float* po   = base + OFF_PO;
    float* hA   = base + OFF_HA;
    float* hB   = base + OFF_HB;
    float* rv   = base + OFF_RV;
    float* Z    = base + OFF_Z;
    float* din2 = base + OFF_DIN2;
    float* cp   = base + OFF_CP;
    float* gxrv = base + OFF_GXRV;
    float* Wcb  = base + OFF_WCB;
    float* Wrv  = base + OFF_WRV;
    float* Wenc = base + OFF_WENC;

    cudaFuncSetAttribute(vocab_mma, cudaFuncAttributeMaxDynamicSharedMemorySize, VSMEM);
    cudaFuncSetAttribute(enc_step, cudaFuncAttributeMaxDynamicSharedMemorySize, 65536);

    // ---- phase A ----
    k_zero<<<(unsigned)((SZ_H + 255)/256), 256>>>(hA, SZ_H);
    {
        size_t n4 = (size_t)B*NT*NP*3*25;
        k_gather_tef<<<(unsigned)((n4 + 255)/256), 256>>>(transe_emb, triple, tef);
    }
    {
        size_t n4 = (size_t)TDEC*B*150;
        k_gather_rv<<<(unsigned)((n4 + 255)/256), 256>>>(word_emb, transe_emb, response, resp_triple, rv, Z);
    }
    {
        size_t nsp = (size_t)VW*(KP/8);
        k_split_W<<<(unsigned)((nsp + 255)/256), 256>>>(out_w, Ws);
    }
    {
        size_t n = (size_t)G4*KC;
        k_build_wcomb<<<(unsigned)((n + 255)/256), 256>>>(Wih_d, Whh_d, Wcb);
    }
    {
        size_t n = (size_t)G3*600;
        k_build_wrv<<<(unsigned)((n + 255)/256), 256>>>(Wih_d, Wrv);
    }
    {
        size_t n = (size_t)G3*GH;
        k_build_wenc<<<(unsigned)((n + 255)/256), 256>>>(Whh_e, Wenc);
    }
    k_triple_score<<<B*NT*NP, 128>>>(tef, triple, wh_w, wh_b, wr_w, wr_b, wt_w, wt_b, sl);
    k_graph_softmax<<<B*NT, 64>>>(sl, tef, sg);
    k_ubg<<<B*NT, 128>>>(sg, ub_w, ub_b, ubg);
    {
        size_t n4 = (size_t)B*PL*125;
        k_post_in<<<(unsigned)((n4 + 255)/256), 256>>>(word_emb, sg, post, post_triple, pin);
    }
    gemm_bias<<<dim3((B*PL)/64, G3/64), 256>>>(pin, Wih_e, bih_e, gxe, B*PL, G3, KE);
    gemm_bias<<<dim3((TDEC*B)/64, G3/64), 256>>>(rv, Wrv, bih_d, gxrv, TDEC*B, G3, 600);

    // ---- phase B: encoder recurrence (1 launch/step, ping-pong h) ----
    for (int t = 0; t < PL; t++) {
        float* hin  = (t & 1) ? hB : hA;
        float* hout = (t & 1) ? hA : hB;
        enc_step<<<8, 512, 65536>>>(hin, Wenc, gxe, bhh_e, hout, po, post_length, t);
    }
    k_h2din2<<<(B*GH)/256, 256>>>(hA, din2);   // PL=128 even -> final h in hA

    // ---- phase C: decoder recurrence (2 launches/step) ----
    for (int t = 0; t < TDEC; t++) {
        const float* gxrv_prev = (t > 0) ? (gxrv + (size_t)(t-1)*B*G3) : gxrv;
        dec_fused<<<B, 256>>>(din2, po, cp, gxrv_prev, bhh_d,
                              wb_w, wb_b, wc_w, wc_b, vb_w, vb_b,
                              ubg, sg, tef, Z, t, t > 0 ? 1 : 0);
        gemm_splitk<<<dim3(G4/64, 8), 256>>>(din2, Wcb, cp, B, G4, KC, 192);
    }
    dec_gates2<<<(B*GH)/256, 256>>>(cp, gxrv + (size_t)(TDEC-1)*B*G3, bhh_d, din2, Z, TDEC-1);

    // ---- phase D: split Z + vocab projection ----
    {
        size_t nsp = (size_t)MP*(KP/8);
        k_split_Z<<<(unsigned)((nsp + 255)/256), 256>>>(Z, As);
    }
    vocab_mma<<<dim3(MP/VTM, VW/VTN), 256, VSMEM>>>(As, Ws, out_b, out);
}

// round 9
// speedup vs baseline: 1.6151x; 1.6151x over previous
#include <cuda_runtime.h>
#include <cuda_bf16.h>
#include <cstdint>
#include <math.h>

// ---------------- problem dims ----------------
#define B    64
#define PL   128
#define RL   64
#define TDEC 63
#define NT   50
#define NP   20
#define TE   100
#define HID  100
#define GH   512
#define G3   1536
#define G4   2048        // 4 gate-row groups for combined decoder GEMM
#define DE   300
#define VW   32000
#define KE   500
#define KD   1612        // logits input dim [hn,dg,tv,rv]
#define KC   1524        // combined decoder GEMM K = 1012 (cv,dg,tv) + 512 (h)
#define NEGV -1000000000.0f
#define NCH  5           // tv n-chunks (10 triples each)

// ---- bf16-split vocab GEMM dims ----
#define KSEG 1612
#define KP   4864
#define MP   4096
#define SSTRIDE 40       // smem row stride in bf16 (32 data + 8 pad)
#define VTM  256
#define VTN  128
#define VSTAGE_A (256*SSTRIDE*2)        // 20480
#define VSTAGE_B (128*SSTRIDE*2)        // 10240
#define VSTAGE   (VSTAGE_A + VSTAGE_B)  // 30720
#define VSMEM    (3*VSTAGE)             // 92160

// ---------------- scratch ----------------
constexpr size_t SZ_TEF = (size_t)B*NT*NP*300;
constexpr size_t SZ_SL  = (size_t)B*NT*NP;
constexpr size_t SZ_SG  = (size_t)B*NT*200;
constexpr size_t SZ_UBG = (size_t)B*NT*100;
constexpr size_t SZ_PIN = (size_t)B*PL*KE;
constexpr size_t SZ_GXE = (size_t)B*PL*G3;
constexpr size_t SZ_PO  = (size_t)B*PL*GH;
constexpr size_t SZ_H   = (size_t)B*GH;
constexpr size_t SZ_RV  = (size_t)TDEC*B*600;
constexpr size_t SZ_Z   = (size_t)TDEC*B*KD;
constexpr size_t SZ_DIN2= (size_t)B*KC;
constexpr size_t SZ_Q   = (size_t)B*300;
constexpr size_t SZ_DA  = (size_t)B*NT;
constexpr size_t SZ_CP  = (size_t)8*B*G4;
constexpr size_t SZ_GHP = (size_t)4*B*G3;
constexpr size_t SZ_GXRV= (size_t)TDEC*B*G3;
constexpr size_t SZ_WCB = (size_t)G4*KC;
constexpr size_t SZ_WRV = (size_t)G3*600;
constexpr size_t SZ_TVP = (size_t)B*NCH*300;

constexpr size_t OFF_TEF = 0;
constexpr size_t OFF_SL  = OFF_TEF + SZ_TEF;
constexpr size_t OFF_SG  = OFF_SL  + SZ_SL;
constexpr size_t OFF_UBG = OFF_SG  + SZ_SG;
constexpr size_t OFF_PIN = OFF_UBG + SZ_UBG;
constexpr size_t OFF_GXE = OFF_PIN + SZ_PIN;
constexpr size_t OFF_PO  = OFF_GXE + SZ_GXE;
constexpr size_t OFF_H   = OFF_PO  + SZ_PO;
constexpr size_t OFF_RV  = OFF_H   + SZ_H;
constexpr size_t OFF_Z   = OFF_RV  + SZ_RV;
constexpr size_t OFF_DIN2= OFF_Z   + SZ_Z;
constexpr size_t OFF_Q   = OFF_DIN2+ SZ_DIN2;
constexpr size_t OFF_DA  = OFF_Q   + SZ_Q;
constexpr size_t OFF_CP  = OFF_DA  + SZ_DA;
constexpr size_t OFF_GHP = OFF_CP  + SZ_CP;
constexpr size_t OFF_GXRV= OFF_GHP + SZ_GHP;
constexpr size_t OFF_WCB = OFF_GXRV+ SZ_GXRV;
constexpr size_t OFF_WRV = OFF_WCB + SZ_WCB;
constexpr size_t OFF_TVP = OFF_WRV + SZ_WRV;
constexpr size_t SZ_TOTAL = OFF_TVP + SZ_TVP;

__device__ float g_buf[SZ_TOTAL];
__device__ __align__(16) __nv_bfloat16 g_Ws[(size_t)VW * KP];
__device__ __align__(16) __nv_bfloat16 g_As[(size_t)MP * KP];

__device__ __forceinline__ float sigmoidf_(float x) { return 1.0f / (1.0f + expf(-x)); }
__device__ __forceinline__ uint32_t smem_u32(const void* p) {
    uint32_t a;
    asm("{ .reg .u64 t; cvta.to.shared.u64 t, %1; cvt.u32.u64 %0, t; }" : "=r"(a) : "l"(p));
    return a;
}

// ---------------- small utility kernels ----------------
__global__ void k_zero(float* p, size_t n) {
    size_t i = (size_t)blockIdx.x*blockDim.x + threadIdx.x;
    if (i < n) p[i] = 0.f;
}

__global__ void k_gather_tef(const float* __restrict__ te, const int* __restrict__ triple,
                             float* __restrict__ tef) {
    size_t i = (size_t)blockIdx.x*blockDim.x + threadIdx.x;
    size_t total = (size_t)B*NT*NP*3*25;
    if (i >= total) return;
    size_t ent = i / 25; int off = (int)(i % 25) * 4;
    size_t tri = ent / 3; int e = (int)(ent % 3);
    int idx = triple[ent];
    float4 v = *reinterpret_cast<const float4*>(te + (size_t)idx*TE + off);
    *reinterpret_cast<float4*>(tef + tri*300 + e*100 + off) = v;
}

__global__ void k_gather_rv(const float* __restrict__ we, const float* __restrict__ te,
                            const int* __restrict__ resp, const int* __restrict__ rtrip,
                            float* __restrict__ rv, float* __restrict__ Z) {
    size_t i = (size_t)blockIdx.x*blockDim.x + threadIdx.x;
    size_t total = (size_t)TDEC*B*150;
    if (i >= total) return;
    size_t tb = i / 150; int f = (int)(i % 150);
    int t = (int)(tb / B), b = (int)(tb % B);
    float4 v;
    if (f < 75) {
        int w = resp[b*RL + t];
        v = *reinterpret_cast<const float4*>(we + (size_t)w*DE + f*4);
    } else {
        int f2 = f - 75; int e = f2 / 25; int off = (f2 % 25) * 4;
        int idx = rtrip[((size_t)b*RL + t)*3 + e];
        v = *reinterpret_cast<const float4*>(te + (size_t)idx*TE + off);
    }
    *reinterpret_cast<float4*>(rv + tb*600 + f*4) = v;
    *reinterpret_cast<float4*>(Z + tb*KD + 1012 + f*4) = v;
}

__global__ void k_triple_score(const float* __restrict__ tef, const int* __restrict__ triple,
                               const float* __restrict__ wh_w, const float* __restrict__ wh_b,
                               const float* __restrict__ wr_w, const float* __restrict__ wr_b,
                               const float* __restrict__ wt_w, const float* __restrict__ wt_b,
                               float* __restrict__ sl) {
    int g = blockIdx.x;
    const float* tb = tef + (size_t)g*300;
    __shared__ float e[300];
    __shared__ float red[128];
    int tid = threadIdx.x;
    for (int i = tid; i < 300; i += 128) e[i] = tb[i];
    __syncthreads();
    float contrib = 0.f;
    if (tid < HID) {
        int j = tid;
        float a = wh_b[j] + wt_b[j];
        float r = wr_b[j];
        const float* whr = wh_w + (size_t)j*TE;
        const float* wtr = wt_w + (size_t)j*TE;
        const float* wrr = wr_w + (size_t)j*TE;
        #pragma unroll 4
        for (int k = 0; k < TE; k++) {
            a += e[k]*whr[k] + e[200+k]*wtr[k];
            r += e[100+k]*wrr[k];
        }
        contrib = r * tanhf(a);
    }
    red[tid] = contrib; __syncthreads();
    for (int s = 64; s; s >>= 1) { if (tid < s) red[tid] += red[tid+s]; __syncthreads(); }
    if (tid == 0)
        sl[g] = (triple[(size_t)g*3] == 0) ? NEGV : red[0];
}

__global__ void k_graph_softmax(const float* __restrict__ sl, const float* __restrict__ tef,
                                float* __restrict__ sg) {
    int g = blockIdx.x;
    int tid = threadIdx.x;
    __shared__ float sa[NP];
    if (tid == 0) {
        float m = -1e30f;
        for (int p = 0; p < NP; p++) m = fmaxf(m, sl[(size_t)g*NP + p]);
        float sum = 0.f;
        for (int p = 0; p < NP; p++) { float ev = expf(sl[(size_t)g*NP + p] - m); sa[p] = ev; sum += ev; }
        float inv = 1.f / sum;
        for (int p = 0; p < NP; p++) sa[p] *= inv;
    }
    __syncthreads();
    const float* tb = tef + (size_t)g*NP*300;
    for (int d = tid; d < 200; d += 64) {
        int dd = (d < 100) ? d : d + 100;
        float s = 0.f;
        #pragma unroll
        for (int p = 0; p < NP; p++) s += sa[p]*tb[(size_t)p*300 + dd];
        sg[(size_t)g*200 + d] = s;
    }
}

__global__ void k_ubg(const float* __restrict__ sg, const float* __restrict__ ub_w,
                      const float* __restrict__ ub_b, float* __restrict__ ubg) {
    int g = blockIdx.x;
    int tid = threadIdx.x;
    __shared__ float s[200];
    for (int i = tid; i < 200; i += 128) s[i] = sg[(size_t)g*200 + i];
    __syncthreads();
    if (tid < HID) {
        float acc = ub_b[tid];
        const float* w = ub_w + (size_t)tid*200;
        #pragma unroll 4
        for (int k = 0; k < 200; k++) acc += s[k]*w[k];
        ubg[(size_t)g*HID + tid] = acc;
    }
}

__global__ void k_post_in(const float* __restrict__ we, const float* __restrict__ sg,
                          const int* __restrict__ post, const int* __restrict__ ptrip,
                          float* __restrict__ pin) {
    size_t i = (size_t)blockIdx.x*blockDim.x + threadIdx.x;
    size_t total = (size_t)B*PL*125;
    if (i >= total) return;
    size_t bt = i / 125; int f = (int)(i % 125);
    float4 v;
    if (f < 75) {
        v = *reinterpret_cast<const float4*>(we + (size_t)post[bt]*DE + f*4);
    } else {
        int b = (int)(bt / PL);
        int n = ptrip[bt];
        v = *reinterpret_cast<const float4*>(sg + ((size_t)b*NT + n)*200 + (f-75)*4);
    }
    *reinterpret_cast<float4*>(pin + bt*KE + f*4) = v;
}

// build W_comb [G4 x KC]
__global__ void k_build_wcomb(const float* __restrict__ Wih, const float* __restrict__ Whh,
                              float* __restrict__ Wc) {
    size_t i = (size_t)blockIdx.x*blockDim.x + threadIdx.x;
    if (i >= (size_t)G4*KC) return;
    int c = (int)(i % KC);
    int r = (int)(i / KC);
    float v = 0.f;
    if (r < 1024) {
        v = (c < 1012) ? Wih[(size_t)r*KD + c] : Whh[(size_t)r*GH + (c - 1012)];
    } else if (r < 1536) {
        if (c < 1012) v = Wih[(size_t)r*KD + c];
    } else {
        if (c >= 1012) v = Whh[(size_t)(r - 512)*GH + (c - 1012)];
    }
    Wc[i] = v;
}

__global__ void k_build_wrv(const float* __restrict__ Wih, float* __restrict__ Wrv) {
    size_t i = (size_t)blockIdx.x*blockDim.x + threadIdx.x;
    if (i >= (size_t)G3*600) return;
    int c = (int)(i % 600);
    int r = (int)(i / 600);
    Wrv[i] = Wih[(size_t)r*KD + 1012 + c];
}

__global__ void k_h2din2(const float* __restrict__ h, float* __restrict__ din2) {
    int i = blockIdx.x*blockDim.x + threadIdx.x;
    if (i >= B*GH) return;
    int b = i / GH, j = i % GH;
    din2[(size_t)b*KC + 1012 + j] = h[i];
}

// ---------------- fp32 tiled GEMMs ----------------
__global__ void gemm_bias(const float* __restrict__ A, const float* __restrict__ W,
                          const float* __restrict__ bias, float* __restrict__ C,
                          int M, int N, int K) {
    __shared__ float As[16][64];
    __shared__ float Ws[16][64];
    int bm = blockIdx.x * 64, bn = blockIdx.y * 64;
    int tid = threadIdx.x;
    int tx = tid & 15, ty = tid >> 4;
    float acc[4][4] = {};
    int r  = tid >> 2;
    int kk = (tid & 3) * 4;
    for (int k0 = 0; k0 < K; k0 += 16) {
        int gk = k0 + kk;
        float4 va = make_float4(0,0,0,0);
        int gm = bm + r;
        if (gm < M) {
            if (gk + 3 < K) va = *reinterpret_cast<const float4*>(A + (size_t)gm*K + gk);
            else { float t0=0,t1=0,t2=0,t3=0;
                   if (gk+0<K) t0=A[(size_t)gm*K+gk+0]; if (gk+1<K) t1=A[(size_t)gm*K+gk+1];
                   if (gk+2<K) t2=A[(size_t)gm*K+gk+2]; if (gk+3<K) t3=A[(size_t)gm*K+gk+3];
                   va = make_float4(t0,t1,t2,t3); }
        }
        As[kk+0][r]=va.x; As[kk+1][r]=va.y; As[kk+2][r]=va.z; As[kk+3][r]=va.w;
        float4 vw = make_float4(0,0,0,0);
        int gn = bn + r;
        if (gn < N) {
            if (gk + 3 < K) vw = *reinterpret_cast<const float4*>(W + (size_t)gn*K + gk);
            else { float t0=0,t1=0,t2=0,t3=0;
                   if (gk+0<K) t0=W[(size_t)gn*K+gk+0]; if (gk+1<K) t1=W[(size_t)gn*K+gk+1];
                   if (gk+2<K) t2=W[(size_t)gn*K+gk+2]; if (gk+3<K) t3=W[(size_t)gn*K+gk+3];
                   vw = make_float4(t0,t1,t2,t3); }
        }
        Ws[kk+0][r]=vw.x; Ws[kk+1][r]=vw.y; Ws[kk+2][r]=vw.z; Ws[kk+3][r]=vw.w;
        __syncthreads();
        #pragma unroll
        for (int k = 0; k < 16; k++) {
            float4 a = *reinterpret_cast<const float4*>(&As[k][ty*4]);
            float4 b = *reinterpret_cast<const float4*>(&Ws[k][tx*4]);
            acc[0][0]+=a.x*b.x; acc[0][1]+=a.x*b.y; acc[0][2]+=a.x*b.z; acc[0][3]+=a.x*b.w;
            acc[1][0]+=a.y*b.x; acc[1][1]+=a.y*b.y; acc[1][2]+=a.y*b.z; acc[1][3]+=a.y*b.w;
            acc[2][0]+=a.z*b.x; acc[2][1]+=a.z*b.y; acc[2][2]+=a.z*b.z; acc[2][3]+=a.z*b.w;
            acc[3][0]+=a.w*b.x; acc[3][1]+=a.w*b.y; acc[3][2]+=a.w*b.z; acc[3][3]+=a.w*b.w;
        }
        __syncthreads();
    }
    #pragma unroll
    for (int i = 0; i < 4; i++) {
        int gm = bm + ty*4 + i; if (gm >= M) continue;
        #pragma unroll
        for (int j = 0; j < 4; j++) {
            int gn = bn + tx*4 + j; if (gn >= N) continue;
            C[(size_t)gm*N + gn] = acc[i][j] + (bias ? bias[gn] : 0.f);
        }
    }
}

__global__ void gemm_splitk(const float* __restrict__ A, const float* __restrict__ W,
                            float* __restrict__ Cp, int M, int N, int K, int kchunk) {
    __shared__ float As[16][64];
    __shared__ float Ws[16][64];
    int z = blockIdx.y;
    int ks = z * kchunk;
    int ke = min(K, ks + kchunk);
    int bn = blockIdx.x * 64;
    int tid = threadIdx.x;
    int tx = tid & 15, ty = tid >> 4;
    float acc[4][4] = {};
    int r  = tid >> 2;
    int kk = (tid & 3) * 4;
    for (int k0 = ks; k0 < ke; k0 += 16) {
        int gk = k0 + kk;
        float4 va = make_float4(0,0,0,0);
        if (r < M) {
            if (gk + 3 < ke) va = *reinterpret_cast<const float4*>(A + (size_t)r*K + gk);
            else { float t0=0,t1=0,t2=0,t3=0;
                   if (gk+0<ke) t0=A[(size_t)r*K+gk+0]; if (gk+1<ke) t1=A[(size_t)r*K+gk+1];
                   if (gk+2<ke) t2=A[(size_t)r*K+gk+2]; if (gk+3<ke) t3=A[(size_t)r*K+gk+3];
                   va = make_float4(t0,t1,t2,t3); }
        }
        As[kk+0][r]=va.x; As[kk+1][r]=va.y; As[kk+2][r]=va.z; As[kk+3][r]=va.w;
        float4 vw = make_float4(0,0,0,0);
        int gn = bn + r;
        if (gn < N) {
            if (gk + 3 < ke) vw = *reinterpret_cast<const float4*>(W + (size_t)gn*K + gk);
            else { float t0=0,t1=0,t2=0,t3=0;
                   if (gk+0<ke) t0=W[(size_t)gn*K+gk+0]; if (gk+1<ke) t1=W[(size_t)gn*K+gk+1];
                   if (gk+2<ke) t2=W[(size_t)gn*K+gk+2]; if (gk+3<ke) t3=W[(size_t)gn*K+gk+3];
                   vw = make_float4(t0,t1,t2,t3); }
        }
        Ws[kk+0][r]=vw.x; Ws[kk+1][r]=vw.y; Ws[kk+2][r]=vw.z; Ws[kk+3][r]=vw.w;
        __syncthreads();
        #pragma unroll
        for (int k = 0; k < 16; k++) {
            float4 a = *reinterpret_cast<const float4*>(&As[k][ty*4]);
            float4 b = *reinterpret_cast<const float4*>(&Ws[k][tx*4]);
            acc[0][0]+=a.x*b.x; acc[0][1]+=a.x*b.y; acc[0][2]+=a.x*b.z; acc[0][3]+=a.x*b.w;
            acc[1][0]+=a.y*b.x; acc[1][1]+=a.y*b.y; acc[1][2]+=a.y*b.z; acc[1][3]+=a.y*b.w;
            acc[2][0]+=a.z*b.x; acc[2][1]+=a.z*b.y; acc[2][2]+=a.z*b.z; acc[2][3]+=a.z*b.w;
            acc[3][0]+=a.w*b.x; acc[3][1]+=a.w*b.y; acc[3][2]+=a.w*b.z; acc[3][3]+=a.w*b.w;
        }
        __syncthreads();
    }
    float* Cz = Cp + (size_t)z*M*N;
    #pragma unroll
    for (int i = 0; i < 4; i++) {
        int gm = ty*4 + i; if (gm >= M) continue;
        #pragma unroll
        for (int j = 0; j < 4; j++) {
            int gn = bn + tx*4 + j; if (gn >= N) continue;
            Cz[(size_t)gm*N + gn] = acc[i][j];
        }
    }
}

// ---------------- encoder step gates ----------------
__global__ void enc_gates(const float* __restrict__ gxe, const float* __restrict__ ghp,
                          const float* __restrict__ bhh, float* __restrict__ h,
                          float* __restrict__ po, const int* __restrict__ post_length, int t) {
    int idx = blockIdx.x*blockDim.x + threadIdx.x;
    if (idx >= B*GH) return;
    int b = idx / GH, j = idx % GH;
    const float* gx = gxe + ((size_t)b*PL + t)*G3;
    float ghr = bhh[j], ghz = bhh[GH+j], ghn = bhh[2*GH+j];
    #pragma unroll
    for (int s = 0; s < 4; s++) {
        const float* p = ghp + ((size_t)s*B + b)*G3;
        ghr += p[j]; ghz += p[GH+j]; ghn += p[2*GH+j];
    }
    float r = sigmoidf_(gx[j] + ghr);
    float z = sigmoidf_(gx[GH+j] + ghz);
    float n = tanhf(gx[2*GH+j] + r*ghn);
    float hold = h[idx];
    float hn = (1.f - z)*n + z*hold;
    bool valid = t < post_length[b];
    h[idx] = valid ? hn : hold;
    po[((size_t)b*PL + t)*GH + j] = valid ? hn : 0.f;
}

// ---------------- decoder: fused attention + misc (one block per b, 256 thr) --------
__global__ void __launch_bounds__(256) dec_am(
        float* __restrict__ din2, const float* __restrict__ po,
        const float* __restrict__ wb_w, const float* __restrict__ wb_b,
        const float* __restrict__ wc_w, const float* __restrict__ wc_b,
        const float* __restrict__ vb_w, const float* __restrict__ vb_b,
        const float* __restrict__ ubg, const float* __restrict__ sg,
        float* __restrict__ q, float* __restrict__ da,
        float* __restrict__ Z, int t) {
    int b = blockIdx.x, tid = threadIdx.x;
    int lane = tid & 31, wid = tid >> 5;
    __shared__ float hs[GH];
    __shared__ float sc2[256];
    __shared__ float sc[PL];
    __shared__ float al[PL];
    __shared__ float wbh[HID];
    __shared__ float dls[NT];
    __shared__ float das[NT];
    for (int i = tid; i < GH; i += 256) hs[i] = din2[(size_t)b*KC + 1012 + i];
    __syncthreads();
    {   // scores: 2 threads per p
        int p = tid >> 1, hf = tid & 1;
        const float* row = po + ((size_t)b*PL + p)*GH + hf*256;
        const float* h2 = hs + hf*256;
        float s = 0.f;
        for (int k = 0; k < 256; k += 4) {
            float4 v = *reinterpret_cast<const float4*>(row + k);
            s += v.x*h2[k] + v.y*h2[k+1] + v.z*h2[k+2] + v.w*h2[k+3];
        }
        sc2[tid] = s;
    }
    __syncthreads();
    if (tid < PL) sc[tid] = sc2[2*tid] + sc2[2*tid+1];
    __syncthreads();
    // q (300) + wbh (100)
    for (int j = tid; j < 400; j += 256) {
        const float* w;
        float acc;
        if (j < 300) { acc = wc_b[j]; w = wc_w + (size_t)j*GH; }
        else         { acc = wb_b[j-300]; w = wb_w + (size_t)(j-300)*GH; }
        for (int k = 0; k < GH; k += 4) {
            float4 v = *reinterpret_cast<const float4*>(w + k);
            acc += v.x*hs[k] + v.y*hs[k+1] + v.z*hs[k+2] + v.w*hs[k+3];
        }
        if (j < 300) q[(size_t)b*300 + j] = acc;
        else wbh[j-300] = acc;
    }
    if (wid == 0) {
        float v0 = sc[lane], v1 = sc[lane+32], v2 = sc[lane+64], v3 = sc[lane+96];
        float m = fmaxf(fmaxf(v0, v1), fmaxf(v2, v3));
        for (int o = 16; o; o >>= 1) m = fmaxf(m, __shfl_xor_sync(0xffffffffu, m, o));
        float e0 = expf(v0-m), e1 = expf(v1-m), e2 = expf(v2-m), e3 = expf(v3-m);
        float s = e0+e1+e2+e3;
        for (int o = 16; o; o >>= 1) s += __shfl_xor_sync(0xffffffffu, s, o);
        float inv = 1.f/s;
        al[lane] = e0*inv; al[lane+32] = e1*inv; al[lane+64] = e2*inv; al[lane+96] = e3*inv;
    }
    __syncthreads();
    for (int d = tid; d < GH; d += 256) {
        float acc = 0.f;
        for (int p = 0; p < PL; p++) acc += al[p]*po[((size_t)b*PL + p)*GH + d];
        din2[(size_t)b*KC + d] = acc;
    }
    if (tid < NT) {
        float s = 0.f;
        const float* u = ubg + ((size_t)b*NT + tid)*HID;
        for (int j = 0; j < HID; j++) s += vb_w[j]*tanhf(wbh[j] + u[j]);
        dls[tid] = s + vb_b[0];
    }
    __syncthreads();
    if (wid == 0) {
        float a0 = (lane < NT) ? dls[lane] : -1e30f;
        float a1 = (lane+32 < NT) ? dls[lane+32] : -1e30f;
        float m = fmaxf(a0, a1);
        for (int o = 16; o; o >>= 1) m = fmaxf(m, __shfl_xor_sync(0xffffffffu, m, o));
        float e0 = (lane < NT) ? expf(a0-m) : 0.f;
        float e1 = (lane+32 < NT) ? expf(a1-m) : 0.f;
        float s = e0 + e1;
        for (int o = 16; o; o >>= 1) s += __shfl_xor_sync(0xffffffffu, s, o);
        float inv = 1.f/s;
        if (lane < NT)    { das[lane] = e0*inv;    da[(size_t)b*NT + lane] = e0*inv; }
        if (lane+32 < NT) { das[lane+32] = e1*inv; da[(size_t)b*NT + lane+32] = e1*inv; }
    }
    __syncthreads();
    float* zrow = Z + ((size_t)t*B + b)*KD;
    for (int d = tid; d < 200; d += 256) {
        float s = 0.f;
        for (int n = 0; n < NT; n++) s += das[n]*sg[((size_t)b*NT + n)*200 + d];
        din2[(size_t)b*KC + 512 + d] = s;
        zrow[512 + d] = s;
    }
}

// ---------------- triple attention: partial over n-chunks (grid B x NCH) ----------
__global__ void __launch_bounds__(256) dec_tv_part(
        const float* __restrict__ tef, const float* __restrict__ q,
        const float* __restrict__ da, float* __restrict__ tvp) {
    int b = blockIdx.x, ch = blockIdx.y;
    int tid = threadIdx.x, lane = tid & 31, wid = tid >> 5;
    __shared__ float qs[300];
    __shared__ float sw[10*NP];      // 200 scores
    __shared__ float dal[10];
    for (int i = tid; i < 300; i += 256) qs[i] = q[(size_t)b*300 + i];
    if (tid < 10) dal[tid] = da[(size_t)b*NT + ch*10 + tid];
    __syncthreads();
    const float* tb = tef + ((size_t)b*NT + ch*10)*NP*300;
    // pass 1: scores, one warp per (n,p) row
    #pragma unroll
    for (int it = 0; it < 25; it++) {
        int pair = wid + 8*it;       // 0..199
        const float* row = tb + (size_t)pair*300;
        float s = 0.f;
        for (int k = lane; k < 300; k += 32) s += row[k]*qs[k];
        #pragma unroll
        for (int o = 16; o; o >>= 1) s += __shfl_down_sync(0xffffffffu, s, o);
        if (lane == 0) sw[pair] = s;
    }
    __syncthreads();
    // per-n softmax, scaled by da
    for (int n = wid; n < 10; n += 8) {
        float v = (lane < NP) ? sw[n*NP + lane] : -1e30f;
        float m = v;
        for (int o = 16; o; o >>= 1) m = fmaxf(m, __shfl_xor_sync(0xffffffffu, m, o));
        float e = (lane < NP) ? expf(v - m) : 0.f;
        float su = e;
        for (int o = 16; o; o >>= 1) su += __shfl_xor_sync(0xffffffffu, su, o);
        if (lane < NP) sw[n*NP + lane] = e * dal[n] / su;
    }
    __syncthreads();
    // pass 2: weighted accumulation over this chunk's 200 rows (L2-hot)
    for (int d = tid; d < 300; d += 256) {
        float acc = 0.f;
        #pragma unroll 8
        for (int r = 0; r < 200; r++) acc += sw[r]*tb[(size_t)r*300 + d];
        tvp[((size_t)b*NCH + ch)*300 + d] = acc;
    }
}

// combine tv partials -> din2 and Z (deterministic fixed-order sum)
__global__ void dec_tvsum(const float* __restrict__ tvp, float* __restrict__ din2,
                          float* __restrict__ Z, int t) {
    int b = blockIdx.x, d = threadIdx.x;   // 300
    float s = 0.f;
    #pragma unroll
    for (int ch = 0; ch < NCH; ch++) s += tvp[((size_t)b*NCH + ch)*300 + d];
    din2[(size_t)b*KC + 712 + d] = s;
    Z[((size_t)t*B + b)*KD + 712 + d] = s;
}

// decoder gates: combined partials + precomputed gx_rv
__global__ void dec_gates2(const float* __restrict__ cp, const float* __restrict__ gxrv_t,
                           const float* __restrict__ bhh, float* __restrict__ din2,
                           float* __restrict__ Z, int t) {
    int idx = blockIdx.x*blockDim.x + threadIdx.x;
    if (idx >= B*GH) return;
    int b = idx / GH, j = idx % GH;
    float cr = 0.f, cz = 0.f, cxn = 0.f, chn = 0.f;
    #pragma unroll
    for (int z = 0; z < 8; z++) {
        const float* p = cp + ((size_t)z*B + b)*G4;
        cr += p[j]; cz += p[512+j]; cxn += p[1024+j]; chn += p[1536+j];
    }
    const float* gr = gxrv_t + (size_t)b*G3;   // includes bih
    float r  = sigmoidf_(cr + gr[j] + bhh[j]);
    float zz = sigmoidf_(cz + gr[GH+j] + bhh[GH+j]);
    float n  = tanhf(cxn + gr[2*GH+j] + r*(chn + bhh[2*GH+j]));
    float hold = din2[(size_t)b*KC + 1012 + j];
    float hn = (1.f - zz)*n + zz*hold;
    din2[(size_t)b*KC + 1012 + j] = hn;
    Z[((size_t)t*B + b)*KD + j] = hn;
}

// ---------------- bf16 split prep ----------------
__global__ void k_split_W(const float* __restrict__ W, __nv_bfloat16* __restrict__ Ws) {
    size_t i = (size_t)blockIdx.x*blockDim.x + threadIdx.x;
    size_t total = (size_t)VW*(KP/8);
    if (i >= total) return;
    int cg = (int)(i % (KP/8));
    size_t r = i / (KP/8);
    int c0 = cg*8;
    __nv_bfloat16 o[8];
    #pragma unroll
    for (int e = 0; e < 8; e++) {
        int c = c0 + e;
        __nv_bfloat16 v = __float2bfloat16(0.f);
        if (c < 2*KSEG) {
            int kc = (c < KSEG) ? c : c - KSEG;
            v = __float2bfloat16(W[r*KSEG + kc]);
        } else if (c < 3*KSEG) {
            float w = W[r*KSEG + c - 2*KSEG];
            __nv_bfloat16 hh = __float2bfloat16(w);
            v = __float2bfloat16(w - __bfloat162float(hh));
        }
        o[e] = v;
    }
    *reinterpret_cast<uint4*>(Ws + r*KP + c0) = *reinterpret_cast<uint4*>(o);
}

__global__ void k_split_Z(const float* __restrict__ Z, __nv_bfloat16* __restrict__ As_) {
    size_t i = (size_t)blockIdx.x*blockDim.x + threadIdx.x;
    size_t total = (size_t)MP*(KP/8);
    if (i >= total) return;
    int cg = (int)(i % (KP/8));
    int m = (int)(i / (KP/8));
    int b = m / TDEC, t = m - b*TDEC;
    int c0 = cg*8;
    __nv_bfloat16 o[8];
    #pragma unroll
    for (int e = 0; e < 8; e++) {
        int c = c0 + e;
        __nv_bfloat16 v = __float2bfloat16(0.f);
        if (b < B && c < 3*KSEG) {
            int kc = (c < KSEG) ? c : (c < 2*KSEG ? c - KSEG : c - 2*KSEG);
            float z = Z[((size_t)t*B + b)*KD + kc];
            __nv_bfloat16 hh = __float2bfloat16(z);
            if (c >= KSEG && c < 2*KSEG) v = __float2bfloat16(z - __bfloat162float(hh));
            else v = hh;
        }
        o[e] = v;
    }
    *reinterpret_cast<uint4*>(As_ + (size_t)m*KP + c0) = *reinterpret_cast<uint4*>(o);
}

// ---------------- mma.sync bf16 vocab GEMM: 256x128 CTA tile, 3-stage ----------------
__global__ void __launch_bounds__(256) vocab_mma(
        const __nv_bfloat16* __restrict__ Ag, const __nv_bfloat16* __restrict__ Wg,
        const float* __restrict__ bout, float* __restrict__ out) {
    extern __shared__ __align__(16) char sraw[];
    const int tid = threadIdx.x;
    const int wid = tid >> 5, lane = tid & 31;
    const int m0 = blockIdx.x * VTM, n0 = blockIdx.y * VTN;
    const int wm = (wid >> 1) * 64, wn = (wid & 1) * 64;
    const int g = lane >> 2, tg = lane & 3;
    const uint32_t sb = smem_u32(sraw);

    float acc[4][8][4];
    #pragma unroll
    for (int i = 0; i < 4; i++)
    #pragma unroll
    for (int j = 0; j < 8; j++) { acc[i][j][0]=0.f; acc[i][j][1]=0.f; acc[i][j][2]=0.f; acc[i][j][3]=0.f; }

    auto load_stage = [&](int s, int k0) {
        uint32_t base = sb + (uint32_t)s*VSTAGE;
        #pragma unroll
        for (int i = 0; i < 6; i++) {
            int c = i*256 + tid;
            int isB = (c >= 1024);
            int cc = isB ? (c - 1024) : c;
            int row = cc >> 2, ch = cc & 3;
            uint32_t dst = base + (isB ? VSTAGE_A : 0u)
                         + (uint32_t)row*(SSTRIDE*2) + (uint32_t)ch*16u;
            const __nv_bfloat16* src = isB ? (Wg + (size_t)(n0+row)*KP + k0 + ch*8)
                                           : (Ag + (size_t)(m0+row)*KP + k0 + ch*8);
            asm volatile("cp.async.cg.shared.global [%0], [%1], 16;" :: "r"(dst), "l"(src));
        }
        asm volatile("cp.async.commit_group;" ::: "memory");
    };

    load_stage(0, 0); load_stage(1, 32); load_stage(2, 64);

    const int a_row = lane & 15;
    const int a_k8  = (lane >> 4) << 3;
    const int b_row = lane & 7;
    const int b_k8  = ((lane >> 3) & 1) << 3;

    const int NIT = KP/32;
    for (int kt = 0; kt < NIT; kt++) {
        if (kt + 3 < NIT) { asm volatile("cp.async.wait_group 2;" ::: "memory"); }
        else              { asm volatile("cp.async.wait_group 0;" ::: "memory"); }
        __syncthreads();
        int s = kt % 3;
        uint32_t baseA = sb + (uint32_t)s*VSTAGE;
        uint32_t baseB = baseA + VSTAGE_A;
        #pragma unroll
        for (int kk = 0; kk < 2; kk++) {
            uint32_t afr[4][4];
            #pragma unroll
            for (int mi = 0; mi < 4; mi++) {
                uint32_t ad = baseA + ((uint32_t)(wm + mi*16 + a_row)*SSTRIDE
                                       + (uint32_t)(kk*16 + a_k8))*2u;
                asm volatile("ldmatrix.sync.aligned.m8n8.x4.shared.b16 {%0,%1,%2,%3}, [%4];"
                    : "=r"(afr[mi][0]),"=r"(afr[mi][1]),"=r"(afr[mi][2]),"=r"(afr[mi][3])
                    : "r"(ad));
            }
            uint32_t bfr[8][2];
            #pragma unroll
            for (int ni = 0; ni < 8; ni++) {
                uint32_t bd = baseB + ((uint32_t)(wn + ni*8 + b_row)*SSTRIDE
                                       + (uint32_t)(kk*16 + b_k8))*2u;
                asm volatile("ldmatrix.sync.aligned.m8n8.x2.shared.b16 {%0,%1}, [%2];"
                    : "=r"(bfr[ni][0]),"=r"(bfr[ni][1]) : "r"(bd));
            }
            #pragma unroll
            for (int mi = 0; mi < 4; mi++)
            #pragma unroll
            for (int ni = 0; ni < 8; ni++) {
                asm volatile(
                  "mma.sync.aligned.m16n8k16.row.col.f32.bf16.bf16.f32 "
                  "{%0,%1,%2,%3},{%4,%5,%6,%7},{%8,%9},{%0,%1,%2,%3};"
                  : "+f"(acc[mi][ni][0]), "+f"(acc[mi][ni][1]),
                    "+f"(acc[mi][ni][2]), "+f"(acc[mi][ni][3])
                  : "r"(afr[mi][0]),"r"(afr[mi][1]),"r"(afr[mi][2]),"r"(afr[mi][3]),
                    "r"(bfr[ni][0]),"r"(bfr[ni][1]));
            }
        }
        __syncthreads();
        if (kt + 3 < NIT) load_stage(s, (kt+3)*32);
    }
    __syncthreads();

    float* Ds = (float*)sraw;
    #pragma unroll
    for (int h = 0; h < 2; h++) {
        if ((wid >> 2) == h) {
            int mbase = wm - h*128;
            #pragma unroll
            for (int mi = 0; mi < 4; mi++) {
                int mA = mbase + mi*16 + g;
                #pragma unroll
                for (int ni = 0; ni < 8; ni++) {
                    int nn = wn + ni*8 + tg*2;
                    Ds[mA*129 + nn]         = acc[mi][ni][0];
                    Ds[mA*129 + nn + 1]     = acc[mi][ni][1];
                    Ds[(mA+8)*129 + nn]     = acc[mi][ni][2];
                    Ds[(mA+8)*129 + nn + 1] = acc[mi][ni][3];
                }
            }
        }
        __syncthreads();
        for (int idx = tid; idx < VTN*128; idx += 256) {
            int n = idx >> 7, m = idx & 127;
            int mg = m0 + h*128 + m;
            if (mg < B*TDEC) {
                int bb = mg / TDEC, tt = mg - bb*TDEC;
                int ng = n0 + n;
                out[(size_t)bb*VW*TDEC + (size_t)ng*TDEC + tt] = Ds[m*129 + n] + __ldg(bout + ng);
            }
        }
        __syncthreads();
    }
}

// ---------------- launch ----------------
extern "C" void kernel_launch(void* const* d_in, const int* in_sizes, int n_in,
                              void* d_out, int out_size) {
    const float* word_emb   = (const float*)d_in[0];
    const float* transe_emb = (const float*)d_in[1];
    const float* wh_w = (const float*)d_in[2];  const float* wh_b = (const float*)d_in[3];
    const float* wr_w = (const float*)d_in[4];  const float* wr_b = (const float*)d_in[5];
    const float* wt_w = (const float*)d_in[6];  const float* wt_b = (const float*)d_in[7];
    const float* wb_w = (const float*)d_in[8];  const float* wb_b = (const float*)d_in[9];
    const float* ub_w = (const float*)d_in[10]; const float* ub_b = (const float*)d_in[11];
    const float* vb_w = (const float*)d_in[12]; const float* vb_b = (const float*)d_in[13];
    const float* wc_w = (const float*)d_in[14]; const float* wc_b = (const float*)d_in[15];
    const float* Wih_e = (const float*)d_in[16]; const float* Whh_e = (const float*)d_in[17];
    const float* bih_e = (const float*)d_in[18]; const float* bhh_e = (const float*)d_in[19];
    const float* Wih_d = (const float*)d_in[20]; const float* Whh_d = (const float*)d_in[21];
    const float* bih_d = (const float*)d_in[22]; const float* bhh_d = (const float*)d_in[23];
    const float* out_w = (const float*)d_in[24]; const float* out_b = (const float*)d_in[25];
    const int* post          = (const int*)d_in[26];
    const int* post_length   = (const int*)d_in[27];
    const int* response      = (const int*)d_in[28];
    const int* resp_triple   = (const int*)d_in[29];
    const int* post_triple   = (const int*)d_in[30];
    const int* triple        = (const int*)d_in[31];
    float* out = (float*)d_out;

    void* basep = nullptr; cudaGetSymbolAddress(&basep, g_buf);
    float* base = (float*)basep;
    void* wsp = nullptr; cudaGetSymbolAddress(&wsp, g_Ws);
    void* asp = nullptr; cudaGetSymbolAddress(&asp, g_As);
    __nv_bfloat16* Ws = (__nv_bfloat16*)wsp;
    __nv_bfloat16* As = (__nv_bfloat16*)asp;

    float* tef  = base + OFF_TEF;
    float* sl   = base + OFF_SL;
    float* sg   = base + OFF_SG;
    float* ubg  = base + OFF_UBG;
    float* pin  = base + OFF_PIN;
    float* gxe  = base + OFF_GXE;
    float* po   = base + OFF_PO;
    float* h    = base + OFF_H;
    float* rv   = base + OFF_RV;
    float* Z    = base + OFF_Z;
    float* din2 = base + OFF_DIN2;
    float* q    = base + OFF_Q;
    float* da   = base + OFF_DA;
    float* cp   = base + OFF_CP;
    float* ghp  = base + OFF_GHP;
    float* gxrv = base + OFF_GXRV;
    float* Wcb  = base + OFF_WCB;
    float* Wrv  = base + OFF_WRV;
    float* tvp  = base + OFF_TVP;

    cudaFuncSetAttribute(vocab_mma, cudaFuncAttributeMaxDynamicSharedMemorySize, VSMEM);

    // ---- phase A ----
    k_zero<<<(unsigned)((SZ_H + 255)/256), 256>>>(h, SZ_H);
    {
        size_t n4 = (size_t)B*NT*NP*3*25;
        k_gather_tef<<<(unsigned)((n4 + 255)/256), 256>>>(transe_emb, triple, tef);
    }
    {
        size_t n4 = (size_t)TDEC*B*150;
        k_gather_rv<<<(unsigned)((n4 + 255)/256), 256>>>(word_emb, transe_emb, response, resp_triple, rv, Z);
    }
    {
        size_t nsp = (size_t)VW*(KP/8);
        k_split_W<<<(unsigned)((nsp + 255)/256), 256>>>(out_w, Ws);
    }
    {
        size_t n = (size_t)G4*KC;
        k_build_wcomb<<<(unsigned)((n + 255)/256), 256>>>(Wih_d, Whh_d, Wcb);
    }
    {
        size_t n = (size_t)G3*600;
        k_build_wrv<<<(unsigned)((n + 255)/256), 256>>>(Wih_d, Wrv);
    }
    k_triple_score<<<B*NT*NP, 128>>>(tef, triple, wh_w, wh_b, wr_w, wr_b, wt_w, wt_b, sl);
    k_graph_softmax<<<B*NT, 64>>>(sl, tef, sg);
    k_ubg<<<B*NT, 128>>>(sg, ub_w, ub_b, ubg);
    {
        size_t n4 = (size_t)B*PL*125;
        k_post_in<<<(unsigned)((n4 + 255)/256), 256>>>(word_emb, sg, post, post_triple, pin);
    }
    gemm_bias<<<dim3((B*PL)/64, G3/64), 256>>>(pin, Wih_e, bih_e, gxe, B*PL, G3, KE);
    gemm_bias<<<dim3((TDEC*B)/64, G3/64), 256>>>(rv, Wrv, bih_d, gxrv, TDEC*B, G3, 600);

    // ---- phase B: encoder recurrence ----
    for (int t = 0; t < PL; t++) {
        gemm_splitk<<<dim3(G3/64, 4), 256>>>(h, Whh_e, ghp, B, G3, GH, 128);
        enc_gates<<<(B*GH)/256, 256>>>(gxe, ghp, bhh_e, h, po, post_length, t);
    }
    k_h2din2<<<(B*GH)/256, 256>>>(h, din2);

    // ---- phase C: decoder recurrence ----
    for (int t = 0; t < TDEC; t++) {
        dec_am<<<B, 256>>>(din2, po, wb_w, wb_b, wc_w, wc_b, vb_w, vb_b, ubg, sg, q, da, Z, t);
        dec_tv_part<<<dim3(B, NCH), 256>>>(tef, q, da, tvp);
        dec_tvsum<<<B, 300>>>(tvp, din2, Z, t);
        gemm_splitk<<<dim3(G4/64, 8), 256>>>(din2, Wcb, cp, B, G4, KC, 192);
        dec_gates2<<<(B*GH)/256, 256>>>(cp, gxrv + (size_t)t*B*G3, bhh_d, din2, Z, t);
    }

    // ---- phase D: split Z + vocab projection ----
    {
        size_t nsp = (size_t)MP*(KP/8);
        k_split_Z<<<(unsigned)((nsp + 255)/256), 256>>>(Z, As);
    }
    vocab_mma<<<dim3(MP/VTM, VW/VTN), 256, VSMEM>>>(As, Ws, out_b, out);
}

// round 10
// speedup vs baseline: 1.8142x; 1.1233x over previous
#include <cuda_runtime.h>
#include <cuda_fp16.h>
#include <cstdint>
#include <math.h>

// ---------------- problem dims ----------------
#define B    64
#define PL   128
#define RL   64
#define TDEC 63
#define NT   50
#define NP   20
#define TE   100
#define HID  100
#define GH   512
#define G3   1536
#define G4   2048        // 4 gate-row groups for combined decoder GEMM
#define DE   300
#define VW   32000
#define KE   500
#define KD   1612        // logits input dim [hn,dg,tv,rv]
#define KC   1524        // combined decoder GEMM K = 1012 (cv,dg,tv) + 512 (h)
#define NEGV -1000000000.0f
#define NCH  5           // tv n-chunks (10 triples each)

// ---- fp16 2-term split vocab GEMM dims: A'=[ah|al], B'=[bh|bh] ----
#define KSEG 1612
#define KP   3264        // 2*1612=3224 padded to 32 multiple
#define MP   4096
#define SSTRIDE 40       // smem row stride in fp16 (32 data + 8 pad)
#define VTM  256
#define VTN  128
#define VSTAGE_A (256*SSTRIDE*2)        // 20480
#define VSTAGE_B (128*SSTRIDE*2)        // 10240
#define VSTAGE   (VSTAGE_A + VSTAGE_B)  // 30720
#define VSMEM    (3*VSTAGE)             // 92160

// ---------------- scratch ----------------
constexpr size_t SZ_TEF = (size_t)B*NT*NP*300;
constexpr size_t SZ_SL  = (size_t)B*NT*NP;
constexpr size_t SZ_SG  = (size_t)B*NT*200;
constexpr size_t SZ_UBG = (size_t)B*NT*100;
constexpr size_t SZ_PIN = (size_t)B*PL*KE;
constexpr size_t SZ_GXE = (size_t)B*PL*G3;
constexpr size_t SZ_PO  = (size_t)B*PL*GH;
constexpr size_t SZ_H   = (size_t)B*GH;
constexpr size_t SZ_RV  = (size_t)TDEC*B*600;
constexpr size_t SZ_Z   = (size_t)TDEC*B*KD;
constexpr size_t SZ_DIN2= (size_t)B*KC;
constexpr size_t SZ_Q   = (size_t)B*300;
constexpr size_t SZ_DA  = (size_t)B*NT;
constexpr size_t SZ_CP  = (size_t)8*B*G4;
constexpr size_t SZ_GHP = (size_t)4*B*G3;
constexpr size_t SZ_GXRV= (size_t)TDEC*B*G3;
constexpr size_t SZ_WCB = (size_t)G4*KC;
constexpr size_t SZ_WRV = (size_t)G3*600;
constexpr size_t SZ_TVP = (size_t)B*NCH*300;

constexpr size_t OFF_TEF = 0;
constexpr size_t OFF_SL  = OFF_TEF + SZ_TEF;
constexpr size_t OFF_SG  = OFF_SL  + SZ_SL;
constexpr size_t OFF_UBG = OFF_SG  + SZ_SG;
constexpr size_t OFF_PIN = OFF_UBG + SZ_UBG;
constexpr size_t OFF_GXE = OFF_PIN + SZ_PIN;
constexpr size_t OFF_PO  = OFF_GXE + SZ_GXE;
constexpr size_t OFF_H   = OFF_PO  + SZ_PO;
constexpr size_t OFF_RV  = OFF_H   + SZ_H;
constexpr size_t OFF_Z   = OFF_RV  + SZ_RV;
constexpr size_t OFF_DIN2= OFF_Z   + SZ_Z;
constexpr size_t OFF_Q   = OFF_DIN2+ SZ_DIN2;
constexpr size_t OFF_DA  = OFF_Q   + SZ_Q;
constexpr size_t OFF_CP  = OFF_DA  + SZ_DA;
constexpr size_t OFF_GHP = OFF_CP  + SZ_CP;
constexpr size_t OFF_GXRV= OFF_GHP + SZ_GHP;
constexpr size_t OFF_WCB = OFF_GXRV+ SZ_GXRV;
constexpr size_t OFF_WRV = OFF_WCB + SZ_WCB;
constexpr size_t OFF_TVP = OFF_WRV + SZ_WRV;
constexpr size_t SZ_TOTAL = OFF_TVP + SZ_TVP;

__device__ float g_buf[SZ_TOTAL];
__device__ __align__(16) __half g_Ws[(size_t)VW * KP];
__device__ __align__(16) __half g_As[(size_t)MP * KP];

__device__ __forceinline__ float sigmoidf_(float x) { return 1.0f / (1.0f + expf(-x)); }
__device__ __forceinline__ uint32_t smem_u32(const void* p) {
    uint32_t a;
    asm("{ .reg .u64 t; cvta.to.shared.u64 t, %1; cvt.u32.u64 %0, t; }" : "=r"(a) : "l"(p));
    return a;
}

// ---------------- small utility kernels ----------------
__global__ void k_zero(float* p, size_t n) {
    size_t i = (size_t)blockIdx.x*blockDim.x + threadIdx.x;
    if (i < n) p[i] = 0.f;
}

__global__ void k_gather_tef(const float* __restrict__ te, const int* __restrict__ triple,
                             float* __restrict__ tef) {
    size_t i = (size_t)blockIdx.x*blockDim.x + threadIdx.x;
    size_t total = (size_t)B*NT*NP*3*25;
    if (i >= total) return;
    size_t ent = i / 25; int off = (int)(i % 25) * 4;
    size_t tri = ent / 3; int e = (int)(ent % 3);
    int idx = triple[ent];
    float4 v = *reinterpret_cast<const float4*>(te + (size_t)idx*TE + off);
    *reinterpret_cast<float4*>(tef + tri*300 + e*100 + off) = v;
}

__global__ void k_gather_rv(const float* __restrict__ we, const float* __restrict__ te,
                            const int* __restrict__ resp, const int* __restrict__ rtrip,
                            float* __restrict__ rv, float* __restrict__ Z) {
    size_t i = (size_t)blockIdx.x*blockDim.x + threadIdx.x;
    size_t total = (size_t)TDEC*B*150;
    if (i >= total) return;
    size_t tb = i / 150; int f = (int)(i % 150);
    int t = (int)(tb / B), b = (int)(tb % B);
    float4 v;
    if (f < 75) {
        int w = resp[b*RL + t];
        v = *reinterpret_cast<const float4*>(we + (size_t)w*DE + f*4);
    } else {
        int f2 = f - 75; int e = f2 / 25; int off = (f2 % 25) * 4;
        int idx = rtrip[((size_t)b*RL + t)*3 + e];
        v = *reinterpret_cast<const float4*>(te + (size_t)idx*TE + off);
    }
    *reinterpret_cast<float4*>(rv + tb*600 + f*4) = v;
    *reinterpret_cast<float4*>(Z + tb*KD + 1012 + f*4) = v;
}

__global__ void k_triple_score(const float* __restrict__ tef, const int* __restrict__ triple,
                               const float* __restrict__ wh_w, const float* __restrict__ wh_b,
                               const float* __restrict__ wr_w, const float* __restrict__ wr_b,
                               const float* __restrict__ wt_w, const float* __restrict__ wt_b,
                               float* __restrict__ sl) {
    int g = blockIdx.x;
    const float* tb = tef + (size_t)g*300;
    __shared__ float e[300];
    __shared__ float red[128];
    int tid = threadIdx.x;
    for (int i = tid; i < 300; i += 128) e[i] = tb[i];
    __syncthreads();
    float contrib = 0.f;
    if (tid < HID) {
        int j = tid;
        float a = wh_b[j] + wt_b[j];
        float r = wr_b[j];
        const float* whr = wh_w + (size_t)j*TE;
        const float* wtr = wt_w + (size_t)j*TE;
        const float* wrr = wr_w + (size_t)j*TE;
        #pragma unroll 4
        for (int k = 0; k < TE; k++) {
            a += e[k]*whr[k] + e[200+k]*wtr[k];
            r += e[100+k]*wrr[k];
        }
        contrib = r * tanhf(a);
    }
    red[tid] = contrib; __syncthreads();
    for (int s = 64; s; s >>= 1) { if (tid < s) red[tid] += red[tid+s]; __syncthreads(); }
    if (tid == 0)
        sl[g] = (triple[(size_t)g*3] == 0) ? NEGV : red[0];
}

__global__ void k_graph_softmax(const float* __restrict__ sl, const float* __restrict__ tef,
                                float* __restrict__ sg) {
    int g = blockIdx.x;
    int tid = threadIdx.x;
    __shared__ float sa[NP];
    if (tid == 0) {
        float m = -1e30f;
        for (int p = 0; p < NP; p++) m = fmaxf(m, sl[(size_t)g*NP + p]);
        float sum = 0.f;
        for (int p = 0; p < NP; p++) { float ev = expf(sl[(size_t)g*NP + p] - m); sa[p] = ev; sum += ev; }
        float inv = 1.f / sum;
        for (int p = 0; p < NP; p++) sa[p] *= inv;
    }
    __syncthreads();
    const float* tb = tef + (size_t)g*NP*300;
    for (int d = tid; d < 200; d += 64) {
        int dd = (d < 100) ? d : d + 100;
        float s = 0.f;
        #pragma unroll
        for (int p = 0; p < NP; p++) s += sa[p]*tb[(size_t)p*300 + dd];
        sg[(size_t)g*200 + d] = s;
    }
}

__global__ void k_ubg(const float* __restrict__ sg, const float* __restrict__ ub_w,
                      const float* __restrict__ ub_b, float* __restrict__ ubg) {
    int g = blockIdx.x;
    int tid = threadIdx.x;
    __shared__ float s[200];
    for (int i = tid; i < 200; i += 128) s[i] = sg[(size_t)g*200 + i];
    __syncthreads();
    if (tid < HID) {
        float acc = ub_b[tid];
        const float* w = ub_w + (size_t)tid*200;
        #pragma unroll 4
        for (int k = 0; k < 200; k++) acc += s[k]*w[k];
        ubg[(size_t)g*HID + tid] = acc;
    }
}

__global__ void k_post_in(const float* __restrict__ we, const float* __restrict__ sg,
                          const int* __restrict__ post, const int* __restrict__ ptrip,
                          float* __restrict__ pin) {
    size_t i = (size_t)blockIdx.x*blockDim.x + threadIdx.x;
    size_t total = (size_t)B*PL*125;
    if (i >= total) return;
    size_t bt = i / 125; int f = (int)(i % 125);
    float4 v;
    if (f < 75) {
        v = *reinterpret_cast<const float4*>(we + (size_t)post[bt]*DE + f*4);
    } else {
        int b = (int)(bt / PL);
        int n = ptrip[bt];
        v = *reinterpret_cast<const float4*>(sg + ((size_t)b*NT + n)*200 + (f-75)*4);
    }
    *reinterpret_cast<float4*>(pin + bt*KE + f*4) = v;
}

// build W_comb [G4 x KC]
__global__ void k_build_wcomb(const float* __restrict__ Wih, const float* __restrict__ Whh,
                              float* __restrict__ Wc) {
    size_t i = (size_t)blockIdx.x*blockDim.x + threadIdx.x;
    if (i >= (size_t)G4*KC) return;
    int c = (int)(i % KC);
    int r = (int)(i / KC);
    float v = 0.f;
    if (r < 1024) {
        v = (c < 1012) ? Wih[(size_t)r*KD + c] : Whh[(size_t)r*GH + (c - 1012)];
    } else if (r < 1536) {
        if (c < 1012) v = Wih[(size_t)r*KD + c];
    } else {
        if (c >= 1012) v = Whh[(size_t)(r - 512)*GH + (c - 1012)];
    }
    Wc[i] = v;
}

__global__ void k_build_wrv(const float* __restrict__ Wih, float* __restrict__ Wrv) {
    size_t i = (size_t)blockIdx.x*blockDim.x + threadIdx.x;
    if (i >= (size_t)G3*600) return;
    int c = (int)(i % 600);
    int r = (int)(i / 600);
    Wrv[i] = Wih[(size_t)r*KD + 1012 + c];
}

__global__ void k_h2din2(const float* __restrict__ h, float* __restrict__ din2) {
    int i = blockIdx.x*blockDim.x + threadIdx.x;
    if (i >= B*GH) return;
    int b = i / GH, j = i % GH;
    din2[(size_t)b*KC + 1012 + j] = h[i];
}

// ---------------- fp32 tiled GEMMs ----------------
__global__ void gemm_bias(const float* __restrict__ A, const float* __restrict__ W,
                          const float* __restrict__ bias, float* __restrict__ C,
                          int M, int N, int K) {
    __shared__ float As[16][64];
    __shared__ float Ws[16][64];
    int bm = blockIdx.x * 64, bn = blockIdx.y * 64;
    int tid = threadIdx.x;
    int tx = tid & 15, ty = tid >> 4;
    float acc[4][4] = {};
    int r  = tid >> 2;
    int kk = (tid & 3) * 4;
    for (int k0 = 0; k0 < K; k0 += 16) {
        int gk = k0 + kk;
        float4 va = make_float4(0,0,0,0);
        int gm = bm + r;
        if (gm < M) {
            if (gk + 3 < K) va = *reinterpret_cast<const float4*>(A + (size_t)gm*K + gk);
            else { float t0=0,t1=0,t2=0,t3=0;
                   if (gk+0<K) t0=A[(size_t)gm*K+gk+0]; if (gk+1<K) t1=A[(size_t)gm*K+gk+1];
                   if (gk+2<K) t2=A[(size_t)gm*K+gk+2]; if (gk+3<K) t3=A[(size_t)gm*K+gk+3];
                   va = make_float4(t0,t1,t2,t3); }
        }
        As[kk+0][r]=va.x; As[kk+1][r]=va.y; As[kk+2][r]=va.z; As[kk+3][r]=va.w;
        float4 vw = make_float4(0,0,0,0);
        int gn = bn + r;
        if (gn < N) {
            if (gk + 3 < K) vw = *reinterpret_cast<const float4*>(W + (size_t)gn*K + gk);
            else { float t0=0,t1=0,t2=0,t3=0;
                   if (gk+0<K) t0=W[(size_t)gn*K+gk+0]; if (gk+1<K) t1=W[(size_t)gn*K+gk+1];
                   if (gk+2<K) t2=W[(size_t)gn*K+gk+2]; if (gk+3<K) t3=W[(size_t)gn*K+gk+3];
                   vw = make_float4(t0,t1,t2,t3); }
        }
        Ws[kk+0][r]=vw.x; Ws[kk+1][r]=vw.y; Ws[kk+2][r]=vw.z; Ws[kk+3][r]=vw.w;
        __syncthreads();
        #pragma unroll
        for (int k = 0; k < 16; k++) {
            float4 a = *reinterpret_cast<const float4*>(&As[k][ty*4]);
            float4 b = *reinterpret_cast<const float4*>(&Ws[k][tx*4]);
            acc[0][0]+=a.x*b.x; acc[0][1]+=a.x*b.y; acc[0][2]+=a.x*b.z; acc[0][3]+=a.x*b.w;
            acc[1][0]+=a.y*b.x; acc[1][1]+=a.y*b.y; acc[1][2]+=a.y*b.z; acc[1][3]+=a.y*b.w;
            acc[2][0]+=a.z*b.x; acc[2][1]+=a.z*b.y; acc[2][2]+=a.z*b.z; acc[2][3]+=a.z*b.w;
            acc[3][0]+=a.w*b.x; acc[3][1]+=a.w*b.y; acc[3][2]+=a.w*b.z; acc[3][3]+=a.w*b.w;
        }
        __syncthreads();
    }
    #pragma unroll
    for (int i = 0; i < 4; i++) {
        int gm = bm + ty*4 + i; if (gm >= M) continue;
        #pragma unroll
        for (int j = 0; j < 4; j++) {
            int gn = bn + tx*4 + j; if (gn >= N) continue;
            C[(size_t)gm*N + gn] = acc[i][j] + (bias ? bias[gn] : 0.f);
        }
    }
}

__global__ void gemm_splitk(const float* __restrict__ A, const float* __restrict__ W,
                            float* __restrict__ Cp, int M, int N, int K, int kchunk) {
    __shared__ float As[16][64];
    __shared__ float Ws[16][64];
    int z = blockIdx.y;
    int ks = z * kchunk;
    int ke = min(K, ks + kchunk);
    int bn = blockIdx.x * 64;
    int tid = threadIdx.x;
    int tx = tid & 15, ty = tid >> 4;
    float acc[4][4] = {};
    int r  = tid >> 2;
    int kk = (tid & 3) * 4;
    for (int k0 = ks; k0 < ke; k0 += 16) {
        int gk = k0 + kk;
        float4 va = make_float4(0,0,0,0);
        if (r < M) {
            if (gk + 3 < ke) va = *reinterpret_cast<const float4*>(A + (size_t)r*K + gk);
            else { float t0=0,t1=0,t2=0,t3=0;
                   if (gk+0<ke) t0=A[(size_t)r*K+gk+0]; if (gk+1<ke) t1=A[(size_t)r*K+gk+1];
                   if (gk+2<ke) t2=A[(size_t)r*K+gk+2]; if (gk+3<ke) t3=A[(size_t)r*K+gk+3];
                   va = make_float4(t0,t1,t2,t3); }
        }
        As[kk+0][r]=va.x; As[kk+1][r]=va.y; As[kk+2][r]=va.z; As[kk+3][r]=va.w;
        float4 vw = make_float4(0,0,0,0);
        int gn = bn + r;
        if (gn < N) {
            if (gk + 3 < ke) vw = *reinterpret_cast<const float4*>(W + (size_t)gn*K + gk);
            else { float t0=0,t1=0,t2=0,t3=0;
                   if (gk+0<ke) t0=W[(size_t)gn*K+gk+0]; if (gk+1<ke) t1=W[(size_t)gn*K+gk+1];
                   if (gk+2<ke) t2=W[(size_t)gn*K+gk+2]; if (gk+3<ke) t3=W[(size_t)gn*K+gk+3];
                   vw = make_float4(t0,t1,t2,t3); }
        }
        Ws[kk+0][r]=vw.x; Ws[kk+1][r]=vw.y; Ws[kk+2][r]=vw.z; Ws[kk+3][r]=vw.w;
        __syncthreads();
        #pragma unroll
        for (int k = 0; k < 16; k++) {
            float4 a = *reinterpret_cast<const float4*>(&As[k][ty*4]);
            float4 b = *reinterpret_cast<const float4*>(&Ws[k][tx*4]);
            acc[0][0]+=a.x*b.x; acc[0][1]+=a.x*b.y; acc[0][2]+=a.x*b.z; acc[0][3]+=a.x*b.w;
            acc[1][0]+=a.y*b.x; acc[1][1]+=a.y*b.y; acc[1][2]+=a.y*b.z; acc[1][3]+=a.y*b.w;
            acc[2][0]+=a.z*b.x; acc[2][1]+=a.z*b.y; acc[2][2]+=a.z*b.z; acc[2][3]+=a.z*b.w;
            acc[3][0]+=a.w*b.x; acc[3][1]+=a.w*b.y; acc[3][2]+=a.w*b.z; acc[3][3]+=a.w*b.w;
        }
        __syncthreads();
    }
    float* Cz = Cp + (size_t)z*M*N;
    #pragma unroll
    for (int i = 0; i < 4; i++) {
        int gm = ty*4 + i; if (gm >= M) continue;
        #pragma unroll
        for (int j = 0; j < 4; j++) {
            int gn = bn + tx*4 + j; if (gn >= N) continue;
            Cz[(size_t)gm*N + gn] = acc[i][j];
        }
    }
}

// ---------------- encoder step gates ----------------
__global__ void enc_gates(const float* __restrict__ gxe, const float* __restrict__ ghp,
                          const float* __restrict__ bhh, float* __restrict__ h,
                          float* __restrict__ po, const int* __restrict__ post_length, int t) {
    int idx = blockIdx.x*blockDim.x + threadIdx.x;
    if (idx >= B*GH) return;
    int b = idx / GH, j = idx % GH;
    const float* gx = gxe + ((size_t)b*PL + t)*G3;
    float ghr = bhh[j], ghz = bhh[GH+j], ghn = bhh[2*GH+j];
    #pragma unroll
    for (int s = 0; s < 4; s++) {
        const float* p = ghp + ((size_t)s*B + b)*G3;
        ghr += p[j]; ghz += p[GH+j]; ghn += p[2*GH+j];
    }
    float r = sigmoidf_(gx[j] + ghr);
    float z = sigmoidf_(gx[GH+j] + ghz);
    float n = tanhf(gx[2*GH+j] + r*ghn);
    float hold = h[idx];
    float hn = (1.f - z)*n + z*hold;
    bool valid = t < post_length[b];
    h[idx] = valid ? hn : hold;
    po[((size_t)b*PL + t)*GH + j] = valid ? hn : 0.f;
}

// ---------------- decoder: prev-gates + attention + misc (one block per b) ---------
__global__ void __launch_bounds__(256) dec_am(
        float* __restrict__ din2, const float* __restrict__ po,
        const float* __restrict__ cp, const float* __restrict__ gxrv_prev,
        const float* __restrict__ bhh,
        const float* __restrict__ wb_w, const float* __restrict__ wb_b,
        const float* __restrict__ wc_w, const float* __restrict__ wc_b,
        const float* __restrict__ vb_w, const float* __restrict__ vb_b,
        const float* __restrict__ ubg, const float* __restrict__ sg,
        float* __restrict__ q, float* __restrict__ da,
        float* __restrict__ Z, int t, int do_gates) {
    int b = blockIdx.x, tid = threadIdx.x;
    int lane = tid & 31, wid = tid >> 5;
    __shared__ float hs[GH];
    __shared__ float sc2[256];
    __shared__ float sc[PL];
    __shared__ float al[PL];
    __shared__ float wbh[HID];
    __shared__ float dls[NT];
    __shared__ float das[NT];
    // phase A: apply gates of step t-1 (known-correct math from R8)
    if (do_gates) {
        #pragma unroll
        for (int jj = 0; jj < 2; jj++) {
            int j = jj*256 + tid;
            float cr = 0.f, cz = 0.f, cxn = 0.f, chn = 0.f;
            #pragma unroll
            for (int z = 0; z < 8; z++) {
                const float* p = cp + ((size_t)z*B + b)*G4;
                cr += p[j]; cz += p[512+j]; cxn += p[1024+j]; chn += p[1536+j];
            }
            const float* gr = gxrv_prev + (size_t)b*G3;
            float r  = sigmoidf_(cr + gr[j] + bhh[j]);
            float zz = sigmoidf_(cz + gr[GH+j] + bhh[GH+j]);
            float n  = tanhf(cxn + gr[2*GH+j] + r*(chn + bhh[2*GH+j]));
            float hold = din2[(size_t)b*KC + 1012 + j];
            float hn = (1.f - zz)*n + zz*hold;
            din2[(size_t)b*KC + 1012 + j] = hn;
            Z[((size_t)(t-1)*B + b)*KD + j] = hn;
            hs[j] = hn;
        }
        __syncthreads();
    } else {
        for (int i = tid; i < GH; i += 256) hs[i] = din2[(size_t)b*KC + 1012 + i];
        __syncthreads();
    }
    {   // scores: 2 threads per p
        int p = tid >> 1, hf = tid & 1;
        const float* row = po + ((size_t)b*PL + p)*GH + hf*256;
        const float* h2 = hs + hf*256;
        float s = 0.f;
        for (int k = 0; k < 256; k += 4) {
            float4 v = *reinterpret_cast<const float4*>(row + k);
            s += v.x*h2[k] + v.y*h2[k+1] + v.z*h2[k+2] + v.w*h2[k+3];
        }
        sc2[tid] = s;
    }
    __syncthreads();
    if (tid < PL) sc[tid] = sc2[2*tid] + sc2[2*tid+1];
    __syncthreads();
    // q (300) + wbh (100)
    for (int j = tid; j < 400; j += 256) {
        const float* w;
        float acc;
        if (j < 300) { acc = wc_b[j]; w = wc_w + (size_t)j*GH; }
        else         { acc = wb_b[j-300]; w = wb_w + (size_t)(j-300)*GH; }
        for (int k = 0; k < GH; k += 4) {
            float4 v = *reinterpret_cast<const float4*>(w + k);
            acc += v.x*hs[k] + v.y*hs[k+1] + v.z*hs[k+2] + v.w*hs[k+3];
        }
        if (j < 300) q[(size_t)b*300 + j] = acc;
        else wbh[j-300] = acc;
    }
    if (wid == 0) {
        float v0 = sc[lane], v1 = sc[lane+32], v2 = sc[lane+64], v3 = sc[lane+96];
        float m = fmaxf(fmaxf(v0, v1), fmaxf(v2, v3));
        for (int o = 16; o; o >>= 1) m = fmaxf(m, __shfl_xor_sync(0xffffffffu, m, o));
        float e0 = expf(v0-m), e1 = expf(v1-m), e2 = expf(v2-m), e3 = expf(v3-m);
        float s = e0+e1+e2+e3;
        for (int o = 16; o; o >>= 1) s += __shfl_xor_sync(0xffffffffu, s, o);
        float inv = 1.f/s;
        al[lane] = e0*inv; al[lane+32] = e1*inv; al[lane+64] = e2*inv; al[lane+96] = e3*inv;
    }
    __syncthreads();
    for (int d = tid; d < GH; d += 256) {
        float acc = 0.f;
        for (int p = 0; p < PL; p++) acc += al[p]*po[((size_t)b*PL + p)*GH + d];
        din2[(size_t)b*KC + d] = acc;
    }
    if (tid < NT) {
        float s = 0.f;
        const float* u = ubg + ((size_t)b*NT + tid)*HID;
        for (int j = 0; j < HID; j++) s += vb_w[j]*tanhf(wbh[j] + u[j]);
        dls[tid] = s + vb_b[0];
    }
    __syncthreads();
    if (wid == 0) {
        float a0 = (lane < NT) ? dls[lane] : -1e30f;
        float a1 = (lane+32 < NT) ? dls[lane+32] : -1e30f;
        float m = fmaxf(a0, a1);
        for (int o = 16; o; o >>= 1) m = fmaxf(m, __shfl_xor_sync(0xffffffffu, m, o));
        float e0 = (lane < NT) ? expf(a0-m) : 0.f;
        float e1 = (lane+32 < NT) ? expf(a1-m) : 0.f;
        float s = e0 + e1;
        for (int o = 16; o; o >>= 1) s += __shfl_xor_sync(0xffffffffu, s, o);
        float inv = 1.f/s;
        if (lane < NT)    { das[lane] = e0*inv;    da[(size_t)b*NT + lane] = e0*inv; }
        if (lane+32 < NT) { das[lane+32] = e1*inv; da[(size_t)b*NT + lane+32] = e1*inv; }
    }
    __syncthreads();
    float* zrow = Z + ((size_t)t*B + b)*KD;
    for (int d = tid; d < 200; d += 256) {
        float s = 0.f;
        for (int n = 0; n < NT; n++) s += das[n]*sg[((size_t)b*NT + n)*200 + d];
        din2[(size_t)b*KC + 512 + d] = s;
        zrow[512 + d] = s;
    }
}

// ---------------- triple attention: partial over n-chunks (grid B x NCH) ----------
__global__ void __launch_bounds__(256) dec_tv_part(
        const float* __restrict__ tef, const float* __restrict__ q,
        const float* __restrict__ da, float* __restrict__ tvp) {
    int b = blockIdx.x, ch = blockIdx.y;
    int tid = threadIdx.x, lane = tid & 31, wid = tid >> 5;
    __shared__ float qs[300];
    __shared__ float sw[10*NP];
    __shared__ float dal[10];
    for (int i = tid; i < 300; i += 256) qs[i] = q[(size_t)b*300 + i];
    if (tid < 10) dal[tid] = da[(size_t)b*NT + ch*10 + tid];
    __syncthreads();
    const float* tb = tef + ((size_t)b*NT + ch*10)*NP*300;
    #pragma unroll
    for (int it = 0; it < 25; it++) {
        int pair = wid + 8*it;
        const float* row = tb + (size_t)pair*300;
        float s = 0.f;
        for (int k = lane; k < 300; k += 32) s += row[k]*qs[k];
        #pragma unroll
        for (int o = 16; o; o >>= 1) s += __shfl_down_sync(0xffffffffu, s, o);
        if (lane == 0) sw[pair] = s;
    }
    __syncthreads();
    for (int n = wid; n < 10; n += 8) {
        float v = (lane < NP) ? sw[n*NP + lane] : -1e30f;
        float m = v;
        for (int o = 16; o; o >>= 1) m = fmaxf(m, __shfl_xor_sync(0xffffffffu, m, o));
        float e = (lane < NP) ? expf(v - m) : 0.f;
        float su = e;
        for (int o = 16; o; o >>= 1) su += __shfl_xor_sync(0xffffffffu, su, o);
        if (lane < NP) sw[n*NP + lane] = e * dal[n] / su;
    }
    __syncthreads();
    for (int d = tid; d < 300; d += 256) {
        float acc = 0.f;
        #pragma unroll 8
        for (int r = 0; r < 200; r++) acc += sw[r]*tb[(size_t)r*300 + d];
        tvp[((size_t)b*NCH + ch)*300 + d] = acc;
    }
}

__global__ void dec_tvsum(const float* __restrict__ tvp, float* __restrict__ din2,
                          float* __restrict__ Z, int t) {
    int b = blockIdx.x, d = threadIdx.x;
    float s = 0.f;
    #pragma unroll
    for (int ch = 0; ch < NCH; ch++) s += tvp[((size_t)b*NCH + ch)*300 + d];
    din2[(size_t)b*KC + 712 + d] = s;
    Z[((size_t)t*B + b)*KD + 712 + d] = s;
}

// final gates for last decoder step
__global__ void dec_gates2(const float* __restrict__ cp, const float* __restrict__ gxrv_t,
                           const float* __restrict__ bhh, float* __restrict__ din2,
                           float* __restrict__ Z, int t) {
    int idx = blockIdx.x*blockDim.x + threadIdx.x;
    if (idx >= B*GH) return;
    int b = idx / GH, j = idx % GH;
    float cr = 0.f, cz = 0.f, cxn = 0.f, chn = 0.f;
    #pragma unroll
    for (int z = 0; z < 8; z++) {
        const float* p = cp + ((size_t)z*B + b)*G4;
        cr += p[j]; cz += p[512+j]; cxn += p[1024+j]; chn += p[1536+j];
    }
    const float* gr = gxrv_t + (size_t)b*G3;
    float r  = sigmoidf_(cr + gr[j] + bhh[j]);
    float zz = sigmoidf_(cz + gr[GH+j] + bhh[GH+j]);
    float n  = tanhf(cxn + gr[2*GH+j] + r*(chn + bhh[2*GH+j]));
    float hold = din2[(size_t)b*KC + 1012 + j];
    float hn = (1.f - zz)*n + zz*hold;
    din2[(size_t)b*KC + 1012 + j] = hn;
    Z[((size_t)t*B + b)*KD + j] = hn;
}

// ---------------- fp16 2-term split prep ----------------
// W row: [bh | bh | 0-pad]; A row: [ah | al | 0-pad]  => A'.B' = ah.bh + al.bh
__global__ void k_split_W(const float* __restrict__ W, __half* __restrict__ Ws) {
    size_t i = (size_t)blockIdx.x*blockDim.x + threadIdx.x;
    size_t total = (size_t)VW*(KP/8);
    if (i >= total) return;
    int cg = (int)(i % (KP/8));
    size_t r = i / (KP/8);
    int c0 = cg*8;
    __half o[8];
    #pragma unroll
    for (int e = 0; e < 8; e++) {
        int c = c0 + e;
        __half v = __float2half(0.f);
        if (c < 2*KSEG) {
            int kc = (c < KSEG) ? c : c - KSEG;
            v = __float2half(W[r*KSEG + kc]);
        }
        o[e] = v;
    }
    *reinterpret_cast<uint4*>(Ws + r*KP + c0) = *reinterpret_cast<uint4*>(o);
}

__global__ void k_split_Z(const float* __restrict__ Z, __half* __restrict__ As_) {
    size_t i = (size_t)blockIdx.x*blockDim.x + threadIdx.x;
    size_t total = (size_t)MP*(KP/8);
    if (i >= total) return;
    int cg = (int)(i % (KP/8));
    int m = (int)(i / (KP/8));
    int b = m / TDEC, t = m - b*TDEC;
    int c0 = cg*8;
    __half o[8];
    #pragma unroll
    for (int e = 0; e < 8; e++) {
        int c = c0 + e;
        __half v = __float2half(0.f);
        if (b < B && c < 2*KSEG) {
            int kc = (c < KSEG) ? c : c - KSEG;
            float z = Z[((size_t)t*B + b)*KD + kc];
            __half hh = __float2half(z);
            if (c >= KSEG) v = __float2half(z - __half2float(hh));
            else v = hh;
        }
        o[e] = v;
    }
    *reinterpret_cast<uint4*>(As_ + (size_t)m*KP + c0) = *reinterpret_cast<uint4*>(o);
}

// ---------------- mma.sync fp16 vocab GEMM: 256x128 CTA tile, 3-stage ----------------
__global__ void __launch_bounds__(256) vocab_mma(
        const __half* __restrict__ Ag, const __half* __restrict__ Wg,
        const float* __restrict__ bout, float* __restrict__ out) {
    extern __shared__ __align__(16) char sraw[];
    const int tid = threadIdx.x;
    const int wid = tid >> 5, lane = tid & 31;
    const int m0 = blockIdx.x * VTM, n0 = blockIdx.y * VTN;
    const int wm = (wid >> 1) * 64, wn = (wid & 1) * 64;
    const int g = lane >> 2, tg = lane & 3;
    const uint32_t sb = smem_u32(sraw);

    float acc[4][8][4];
    #pragma unroll
    for (int i = 0; i < 4; i++)
    #pragma unroll
    for (int j = 0; j < 8; j++) { acc[i][j][0]=0.f; acc[i][j][1]=0.f; acc[i][j][2]=0.f; acc[i][j][3]=0.f; }

    auto load_stage = [&](int s, int k0) {
        uint32_t base = sb + (uint32_t)s*VSTAGE;
        #pragma unroll
        for (int i = 0; i < 6; i++) {
            int c = i*256 + tid;
            int isB = (c >= 1024);
            int cc = isB ? (c - 1024) : c;
            int row = cc >> 2, ch = cc & 3;
            uint32_t dst = base + (isB ? VSTAGE_A : 0u)
                         + (uint32_t)row*(SSTRIDE*2) + (uint32_t)ch*16u;
            const __half* src = isB ? (Wg + (size_t)(n0+row)*KP + k0 + ch*8)
                                    : (Ag + (size_t)(m0+row)*KP + k0 + ch*8);
            asm volatile("cp.async.cg.shared.global [%0], [%1], 16;" :: "r"(dst), "l"(src));
        }
        asm volatile("cp.async.commit_group;" ::: "memory");
    };

    load_stage(0, 0); load_stage(1, 32); load_stage(2, 64);

    const int a_row = lane & 15;
    const int a_k8  = (lane >> 4) << 3;
    const int b_row = lane & 7;
    const int b_k8  = ((lane >> 3) & 1) << 3;

    const int NIT = KP/32;                        // 102
    for (int kt = 0; kt < NIT; kt++) {
        if (kt + 3 < NIT) { asm volatile("cp.async.wait_group 2;" ::: "memory"); }
        else              { asm volatile("cp.async.wait_group 0;" ::: "memory"); }
        __syncthreads();
        int s = kt % 3;
        uint32_t baseA = sb + (uint32_t)s*VSTAGE;
        uint32_t baseB = baseA + VSTAGE_A;
        #pragma unroll
        for (int kk = 0; kk < 2; kk++) {
            uint32_t afr[4][4];
            #pragma unroll
            for (int mi = 0; mi < 4; mi++) {
                uint32_t ad = baseA + ((uint32_t)(wm + mi*16 + a_row)*SSTRIDE
                                       + (uint32_t)(kk*16 + a_k8))*2u;
                asm volatile("ldmatrix.sync.aligned.m8n8.x4.shared.b16 {%0,%1,%2,%3}, [%4];"
                    : "=r"(afr[mi][0]),"=r"(afr[mi][1]),"=r"(afr[mi][2]),"=r"(afr[mi][3])
                    : "r"(ad));
            }
            uint32_t bfr[8][2];
            #pragma unroll
            for (int ni = 0; ni < 8; ni++) {
                uint32_t bd = baseB + ((uint32_t)(wn + ni*8 + b_row)*SSTRIDE
                                       + (uint32_t)(kk*16 + b_k8))*2u;
                asm volatile("ldmatrix.sync.aligned.m8n8.x2.shared.b16 {%0,%1}, [%2];"
                    : "=r"(bfr[ni][0]),"=r"(bfr[ni][1]) : "r"(bd));
            }
            #pragma unroll
            for (int mi = 0; mi < 4; mi++)
            #pragma unroll
            for (int ni = 0; ni < 8; ni++) {
                asm volatile(
                  "mma.sync.aligned.m16n8k16.row.col.f32.f16.f16.f32 "
                  "{%0,%1,%2,%3},{%4,%5,%6,%7},{%8,%9},{%0,%1,%2,%3};"
                  : "+f"(acc[mi][ni][0]), "+f"(acc[mi][ni][1]),
                    "+f"(acc[mi][ni][2]), "+f"(acc[mi][ni][3])
                  : "r"(afr[mi][0]),"r"(afr[mi][1]),"r"(afr[mi][2]),"r"(afr[mi][3]),
                    "r"(bfr[ni][0]),"r"(bfr[ni][1]));
            }
        }
        __syncthreads();
        if (kt + 3 < NIT) load_stage(s, (kt+3)*32);
    }
    __syncthreads();

    float* Ds = (float*)sraw;
    #pragma unroll
    for (int h = 0; h < 2; h++) {
        if ((wid >> 2) == h) {
            int mbase = wm - h*128;
            #pragma unroll
            for (int mi = 0; mi < 4; mi++) {
                int mA = mbase + mi*16 + g;
                #pragma unroll
                for (int ni = 0; ni < 8; ni++) {
                    int nn = wn + ni*8 + tg*2;
                    Ds[mA*129 + nn]         = acc[mi][ni][0];
                    Ds[mA*129 + nn + 1]     = acc[mi][ni][1];
                    Ds[(mA+8)*129 + nn]     = acc[mi][ni][2];
                    Ds[(mA+8)*129 + nn + 1] = acc[mi][ni][3];
                }
            }
        }
        __syncthreads();
        for (int idx = tid; idx < VTN*128; idx += 256) {
            int n = idx >> 7, m = idx & 127;
            int mg = m0 + h*128 + m;
            if (mg < B*TDEC) {
                int bb = mg / TDEC, tt = mg - bb*TDEC;
                int ng = n0 + n;
                out[(size_t)bb*VW*TDEC + (size_t)ng*TDEC + tt] = Ds[m*129 + n] + __ldg(bout + ng);
            }
        }
        __syncthreads();
    }
}

// ---------------- launch ----------------
extern "C" void kernel_launch(void* const* d_in, const int* in_sizes, int n_in,
                              void* d_out, int out_size) {
    const float* word_emb   = (const float*)d_in[0];
    const float* transe_emb = (const float*)d_in[1];
    const float* wh_w = (const float*)d_in[2];  const float* wh_b = (const float*)d_in[3];
    const float* wr_w = (const float*)d_in[4];  const float* wr_b = (const float*)d_in[5];
    const float* wt_w = (const float*)d_in[6];  const float* wt_b = (const float*)d_in[7];
    const float* wb_w = (const float*)d_in[8];  const float* wb_b = (const float*)d_in[9];
    const float* ub_w = (const float*)d_in[10]; const float* ub_b = (const float*)d_in[11];
    const float* vb_w = (const float*)d_in[12]; const float* vb_b = (const float*)d_in[13];
    const float* wc_w = (const float*)d_in[14]; const float* wc_b = (const float*)d_in[15];
    const float* Wih_e = (const float*)d_in[16]; const float* Whh_e = (const float*)d_in[17];
    const float* bih_e = (const float*)d_in[18]; const float* bhh_e = (const float*)d_in[19];
    const float* Wih_d = (const float*)d_in[20]; const float* Whh_d = (const float*)d_in[21];
    const float* bih_d = (const float*)d_in[22]; const float* bhh_d = (const float*)d_in[23];
    const float* out_w = (const float*)d_in[24]; const float* out_b = (const float*)d_in[25];
    const int* post          = (const int*)d_in[26];
    const int* post_length   = (const int*)d_in[27];
    const int* response      = (const int*)d_in[28];
    const int* resp_triple   = (const int*)d_in[29];
    const int* post_triple   = (const int*)d_in[30];
    const int* triple        = (const int*)d_in[31];
    float* out = (float*)d_out;

    void* basep = nullptr; cudaGetSymbolAddress(&basep, g_buf);
    float* base = (float*)basep;
    void* wsp = nullptr; cudaGetSymbolAddress(&wsp, g_Ws);
    void* asp = nullptr; cudaGetSymbolAddress(&asp, g_As);
    __half* Ws = (__half*)wsp;
    __half* As = (__half*)asp;

    float* tef  = base + OFF_TEF;
    float* sl   = base + OFF_SL;
    float* sg   = base + OFF_SG;
    float* ubg  = base + OFF_UBG;
    float* pin  = base + OFF_PIN;
    float* gxe  = base + OFF_GXE;
    float* po   = base + OFF_PO;
    float* h    = base + OFF_H;
    float* rv   = base + OFF_RV;
    float* Z    = base + OFF_Z;
    float* din2 = base + OFF_DIN2;
    float* q    = base + OFF_Q;
    float* da   = base + OFF_DA;
    float* cp   = base + OFF_CP;
    float* ghp  = base + OFF_GHP;
    float* gxrv = base + OFF_GXRV;
    float* Wcb  = base + OFF_WCB;
    float* Wrv  = base + OFF_WRV;
    float* tvp  = base + OFF_TVP;

    cudaFuncSetAttribute(vocab_mma, cudaFuncAttributeMaxDynamicSharedMemorySize, VSMEM);

    // ---- phase A ----
    k_zero<<<(unsigned)((SZ_H + 255)/256), 256>>>(h, SZ_H);
    {
        size_t n4 = (size_t)B*NT*NP*3*25;
        k_gather_tef<<<(unsigned)((n4 + 255)/256), 256>>>(transe_emb, triple, tef);
    }
    {
        size_t n4 = (size_t)TDEC*B*150;
        k_gather_rv<<<(unsigned)((n4 + 255)/256), 256>>>(word_emb, transe_emb, response, resp_triple, rv, Z);
    }
    {
        size_t nsp = (size_t)VW*(KP/8);
        k_split_W<<<(unsigned)((nsp + 255)/256), 256>>>(out_w, Ws);
    }
    {
        size_t n = (size_t)G4*KC;
        k_build_wcomb<<<(unsigned)((n + 255)/256), 256>>>(Wih_d, Whh_d, Wcb);
    }
    {
        size_t n = (size_t)G3*600;
        k_build_wrv<<<(unsigned)((n + 255)/256), 256>>>(Wih_d, Wrv);
    }
    k_triple_score<<<B*NT*NP, 128>>>(tef, triple, wh_w, wh_b, wr_w, wr_b, wt_w, wt_b, sl);
    k_graph_softmax<<<B*NT, 64>>>(sl, tef, sg);
    k_ubg<<<B*NT, 128>>>(sg, ub_w, ub_b, ubg);
    {
        size_t n4 = (size_t)B*PL*125;
        k_post_in<<<(unsigned)((n4 + 255)/256), 256>>>(word_emb, sg, post, post_triple, pin);
    }
    gemm_bias<<<dim3((B*PL)/64, G3/64), 256>>>(pin, Wih_e, bih_e, gxe, B*PL, G3, KE);
    gemm_bias<<<dim3((TDEC*B)/64, G3/64), 256>>>(rv, Wrv, bih_d, gxrv, TDEC*B, G3, 600);

    // ---- phase B: encoder recurrence ----
    for (int t = 0; t < PL; t++) {
        gemm_splitk<<<dim3(G3/64, 4), 256>>>(h, Whh_e, ghp, B, G3, GH, 128);
        enc_gates<<<(B*GH)/256, 256>>>(gxe, ghp, bhh_e, h, po, post_length, t);
    }
    k_h2din2<<<(B*GH)/256, 256>>>(h, din2);

    // ---- phase C: decoder recurrence (4 launches/step) ----
    for (int t = 0; t < TDEC; t++) {
        const float* gxrv_prev = (t > 0) ? (gxrv + (size_t)(t-1)*B*G3) : gxrv;
        dec_am<<<B, 256>>>(din2, po, cp, gxrv_prev, bhh_d,
                           wb_w, wb_b, wc_w, wc_b, vb_w, vb_b,
                           ubg, sg, q, da, Z, t, t > 0 ? 1 : 0);
        dec_tv_part<<<dim3(B, NCH), 256>>>(tef, q, da, tvp);
        dec_tvsum<<<B, 300>>>(tvp, din2, Z, t);
        gemm_splitk<<<dim3(G4/64, 8), 256>>>(din2, Wcb, cp, B, G4, KC, 192);
    }
    dec_gates2<<<(B*GH)/256, 256>>>(cp, gxrv + (size_t)(TDEC-1)*B*G3, bhh_d, din2, Z, TDEC-1);

    // ---- phase D: split Z + vocab projection ----
    {
        size_t nsp = (size_t)MP*(KP/8);
        k_split_Z<<<(unsigned)((nsp + 255)/256), 256>>>(Z, As);
    }
    vocab_mma<<<dim3(MP/VTM, VW/VTN), 256, VSMEM>>>(As, Ws, out_b, out);
}

// round 11
// speedup vs baseline: 1.9104x; 1.0530x over previous
#include <cuda_runtime.h>
#include <cuda_fp16.h>
#include <cstdint>
#include <math.h>

// ---------------- problem dims ----------------
#define B    64
#define PL   128
#define RL   64
#define TDEC 63
#define NT   50
#define NP   20
#define TE   100
#define HID  100
#define GH   512
#define G3   1536
#define G4   2048        // 4 gate-row groups for combined decoder GEMM
#define DE   300
#define VW   32000
#define KE   500
#define KD   1612        // logits input dim [hn,dg,tv,rv]
#define KC   1524        // combined decoder GEMM K = 1012 (cv,dg,tv) + 512 (h)
#define NEGV -1000000000.0f
#define NCH  5           // tv n-chunks (10 triples each)

// ---- fp16 2-term split vocab GEMM dims: A'=[ah|al], B'=[bh|bh] ----
#define KSEG 1612
#define KP   3264        // 2*1612=3224 padded to 32 multiple
#define MP   4096
#define SSTRIDE 40       // smem row stride in fp16 (32 data + 8 pad)
#define VTM  256
#define VTN  128
#define VSTAGE_A (256*SSTRIDE*2)        // 20480
#define VSTAGE_B (128*SSTRIDE*2)        // 10240
#define VSTAGE   (VSTAGE_A + VSTAGE_B)  // 30720
#define VSMEM    (3*VSTAGE)             // 92160

// ---------------- scratch ----------------
constexpr size_t SZ_TEF = (size_t)B*NT*NP*300;
constexpr size_t SZ_SL  = (size_t)B*NT*NP;
constexpr size_t SZ_SG  = (size_t)B*NT*200;
constexpr size_t SZ_UBG = (size_t)B*NT*100;
constexpr size_t SZ_PIN = (size_t)B*PL*KE;
constexpr size_t SZ_GXE = (size_t)B*PL*G3;
constexpr size_t SZ_PO  = (size_t)B*PL*GH;
constexpr size_t SZ_H   = (size_t)B*GH;
constexpr size_t SZ_RV  = (size_t)TDEC*B*600;
constexpr size_t SZ_Z   = (size_t)TDEC*B*KD;
constexpr size_t SZ_DIN2= (size_t)B*KC;
constexpr size_t SZ_Q   = (size_t)B*300;
constexpr size_t SZ_DA  = (size_t)B*NT;
constexpr size_t SZ_CP  = (size_t)8*B*G4;
constexpr size_t SZ_GHP = (size_t)4*B*G3;
constexpr size_t SZ_GXRV= (size_t)TDEC*B*G3;
constexpr size_t SZ_WCB = (size_t)G4*KC;
constexpr size_t SZ_WRV = (size_t)G3*600;
constexpr size_t SZ_TVP = (size_t)B*NCH*300;

constexpr size_t OFF_TEF = 0;
constexpr size_t OFF_SL  = OFF_TEF + SZ_TEF;
constexpr size_t OFF_SG  = OFF_SL  + SZ_SL;
constexpr size_t OFF_UBG = OFF_SG  + SZ_SG;
constexpr size_t OFF_PIN = OFF_UBG + SZ_UBG;
constexpr size_t OFF_GXE = OFF_PIN + SZ_PIN;
constexpr size_t OFF_PO  = OFF_GXE + SZ_GXE;
constexpr size_t OFF_H   = OFF_PO  + SZ_PO;
constexpr size_t OFF_RV  = OFF_H   + SZ_H;
constexpr size_t OFF_Z   = OFF_RV  + SZ_RV;
constexpr size_t OFF_DIN2= OFF_Z   + SZ_Z;
constexpr size_t OFF_Q   = OFF_DIN2+ SZ_DIN2;
constexpr size_t OFF_DA  = OFF_Q   + SZ_Q;
constexpr size_t OFF_CP  = OFF_DA  + SZ_DA;
constexpr size_t OFF_GHP = OFF_CP  + SZ_CP;
constexpr size_t OFF_GXRV= OFF_GHP + SZ_GHP;
constexpr size_t OFF_WCB = OFF_GXRV+ SZ_GXRV;
constexpr size_t OFF_WRV = OFF_WCB + SZ_WCB;
constexpr size_t OFF_TVP = OFF_WRV + SZ_WRV;
constexpr size_t SZ_TOTAL = OFF_TVP + SZ_TVP;

__device__ float g_buf[SZ_TOTAL];
__device__ __align__(16) __half g_Ws[(size_t)VW * KP];
__device__ __align__(16) __half g_As[(size_t)MP * KP];
__device__ __align__(16) __half g_tef16[SZ_TEF];   // fp16 copy of tef for tv passes

__device__ __forceinline__ float sigmoidf_(float x) { return 1.0f / (1.0f + expf(-x)); }
__device__ __forceinline__ uint32_t smem_u32(const void* p) {
    uint32_t a;
    asm("{ .reg .u64 t; cvta.to.shared.u64 t, %1; cvt.u32.u64 %0, t; }" : "=r"(a) : "l"(p));
    return a;
}

// ---------------- small utility kernels ----------------
__global__ void k_zero(float* p, size_t n) {
    size_t i = (size_t)blockIdx.x*blockDim.x + threadIdx.x;
    if (i < n) p[i] = 0.f;
}

__global__ void k_gather_tef(const float* __restrict__ te, const int* __restrict__ triple,
                             float* __restrict__ tef, __half* __restrict__ tef16) {
    size_t i = (size_t)blockIdx.x*blockDim.x + threadIdx.x;
    size_t total = (size_t)B*NT*NP*3*25;
    if (i >= total) return;
    size_t ent = i / 25; int off = (int)(i % 25) * 4;
    size_t tri = ent / 3; int e = (int)(ent % 3);
    int idx = triple[ent];
    float4 v = *reinterpret_cast<const float4*>(te + (size_t)idx*TE + off);
    size_t dst = tri*300 + e*100 + off;
    *reinterpret_cast<float4*>(tef + dst) = v;
    __half h4[4];
    h4[0] = __float2half(v.x); h4[1] = __float2half(v.y);
    h4[2] = __float2half(v.z); h4[3] = __float2half(v.w);
    *reinterpret_cast<uint2*>(tef16 + dst) = *reinterpret_cast<uint2*>(h4);
}

__global__ void k_gather_rv(const float* __restrict__ we, const float* __restrict__ te,
                            const int* __restrict__ resp, const int* __restrict__ rtrip,
                            float* __restrict__ rv, float* __restrict__ Z) {
    size_t i = (size_t)blockIdx.x*blockDim.x + threadIdx.x;
    size_t total = (size_t)TDEC*B*150;
    if (i >= total) return;
    size_t tb = i / 150; int f = (int)(i % 150);
    int t = (int)(tb / B), b = (int)(tb % B);
    float4 v;
    if (f < 75) {
        int w = resp[b*RL + t];
        v = *reinterpret_cast<const float4*>(we + (size_t)w*DE + f*4);
    } else {
        int f2 = f - 75; int e = f2 / 25; int off = (f2 % 25) * 4;
        int idx = rtrip[((size_t)b*RL + t)*3 + e];
        v = *reinterpret_cast<const float4*>(te + (size_t)idx*TE + off);
    }
    *reinterpret_cast<float4*>(rv + tb*600 + f*4) = v;
    *reinterpret_cast<float4*>(Z + tb*KD + 1012 + f*4) = v;
}

__global__ void k_triple_score(const float* __restrict__ tef, const int* __restrict__ triple,
                               const float* __restrict__ wh_w, const float* __restrict__ wh_b,
                               const float* __restrict__ wr_w, const float* __restrict__ wr_b,
                               const float* __restrict__ wt_w, const float* __restrict__ wt_b,
                               float* __restrict__ sl) {
    int g = blockIdx.x;
    const float* tb = tef + (size_t)g*300;
    __shared__ float e[300];
    __shared__ float red[128];
    int tid = threadIdx.x;
    for (int i = tid; i < 300; i += 128) e[i] = tb[i];
    __syncthreads();
    float contrib = 0.f;
    if (tid < HID) {
        int j = tid;
        float a = wh_b[j] + wt_b[j];
        float r = wr_b[j];
        const float* whr = wh_w + (size_t)j*TE;
        const float* wtr = wt_w + (size_t)j*TE;
        const float* wrr = wr_w + (size_t)j*TE;
        #pragma unroll 4
        for (int k = 0; k < TE; k++) {
            a += e[k]*whr[k] + e[200+k]*wtr[k];
            r += e[100+k]*wrr[k];
        }
        contrib = r * tanhf(a);
    }
    red[tid] = contrib; __syncthreads();
    for (int s = 64; s; s >>= 1) { if (tid < s) red[tid] += red[tid+s]; __syncthreads(); }
    if (tid == 0)
        sl[g] = (triple[(size_t)g*3] == 0) ? NEGV : red[0];
}

__global__ void k_graph_softmax(const float* __restrict__ sl, const float* __restrict__ tef,
                                float* __restrict__ sg) {
    int g = blockIdx.x;
    int tid = threadIdx.x;
    __shared__ float sa[NP];
    if (tid == 0) {
        float m = -1e30f;
        for (int p = 0; p < NP; p++) m = fmaxf(m, sl[(size_t)g*NP + p]);
        float sum = 0.f;
        for (int p = 0; p < NP; p++) { float ev = expf(sl[(size_t)g*NP + p] - m); sa[p] = ev; sum += ev; }
        float inv = 1.f / sum;
        for (int p = 0; p < NP; p++) sa[p] *= inv;
    }
    __syncthreads();
    const float* tb = tef + (size_t)g*NP*300;
    for (int d = tid; d < 200; d += 64) {
        int dd = (d < 100) ? d : d + 100;
        float s = 0.f;
        #pragma unroll
        for (int p = 0; p < NP; p++) s += sa[p]*tb[(size_t)p*300 + dd];
        sg[(size_t)g*200 + d] = s;
    }
}

__global__ void k_ubg(const float* __restrict__ sg, const float* __restrict__ ub_w,
                      const float* __restrict__ ub_b, float* __restrict__ ubg) {
    int g = blockIdx.x;
    int tid = threadIdx.x;
    __shared__ float s[200];
    for (int i = tid; i < 200; i += 128) s[i] = sg[(size_t)g*200 + i];
    __syncthreads();
    if (tid < HID) {
        float acc = ub_b[tid];
        const float* w = ub_w + (size_t)tid*200;
        #pragma unroll 4
        for (int k = 0; k < 200; k++) acc += s[k]*w[k];
        ubg[(size_t)g*HID + tid] = acc;
    }
}

__global__ void k_post_in(const float* __restrict__ we, const float* __restrict__ sg,
                          const int* __restrict__ post, const int* __restrict__ ptrip,
                          float* __restrict__ pin) {
    size_t i = (size_t)blockIdx.x*blockDim.x + threadIdx.x;
    size_t total = (size_t)B*PL*125;
    if (i >= total) return;
    size_t bt = i / 125; int f = (int)(i % 125);
    float4 v;
    if (f < 75) {
        v = *reinterpret_cast<const float4*>(we + (size_t)post[bt]*DE + f*4);
    } else {
        int b = (int)(bt / PL);
        int n = ptrip[bt];
        v = *reinterpret_cast<const float4*>(sg + ((size_t)b*NT + n)*200 + (f-75)*4);
    }
    *reinterpret_cast<float4*>(pin + bt*KE + f*4) = v;
}

// build W_comb [G4 x KC]
__global__ void k_build_wcomb(const float* __restrict__ Wih, const float* __restrict__ Whh,
                              float* __restrict__ Wc) {
    size_t i = (size_t)blockIdx.x*blockDim.x + threadIdx.x;
    if (i >= (size_t)G4*KC) return;
    int c = (int)(i % KC);
    int r = (int)(i / KC);
    float v = 0.f;
    if (r < 1024) {
        v = (c < 1012) ? Wih[(size_t)r*KD + c] : Whh[(size_t)r*GH + (c - 1012)];
    } else if (r < 1536) {
        if (c < 1012) v = Wih[(size_t)r*KD + c];
    } else {
        if (c >= 1012) v = Whh[(size_t)(r - 512)*GH + (c - 1012)];
    }
    Wc[i] = v;
}

__global__ void k_build_wrv(const float* __restrict__ Wih, float* __restrict__ Wrv) {
    size_t i = (size_t)blockIdx.x*blockDim.x + threadIdx.x;
    if (i >= (size_t)G3*600) return;
    int c = (int)(i % 600);
    int r = (int)(i / 600);
    Wrv[i] = Wih[(size_t)r*KD + 1012 + c];
}

__global__ void k_h2din2(const float* __restrict__ h, float* __restrict__ din2) {
    int i = blockIdx.x*blockDim.x + threadIdx.x;
    if (i >= B*GH) return;
    int b = i / GH, j = i % GH;
    din2[(size_t)b*KC + 1012 + j] = h[i];
}

// ---------------- fp32 tiled GEMMs ----------------
__global__ void gemm_bias(const float* __restrict__ A, const float* __restrict__ W,
                          const float* __restrict__ bias, float* __restrict__ C,
                          int M, int N, int K) {
    __shared__ float As[16][64];
    __shared__ float Ws[16][64];
    int bm = blockIdx.x * 64, bn = blockIdx.y * 64;
    int tid = threadIdx.x;
    int tx = tid & 15, ty = tid >> 4;
    float acc[4][4] = {};
    int r  = tid >> 2;
    int kk = (tid & 3) * 4;
    for (int k0 = 0; k0 < K; k0 += 16) {
        int gk = k0 + kk;
        float4 va = make_float4(0,0,0,0);
        int gm = bm + r;
        if (gm < M) {
            if (gk + 3 < K) va = *reinterpret_cast<const float4*>(A + (size_t)gm*K + gk);
            else { float t0=0,t1=0,t2=0,t3=0;
                   if (gk+0<K) t0=A[(size_t)gm*K+gk+0]; if (gk+1<K) t1=A[(size_t)gm*K+gk+1];
                   if (gk+2<K) t2=A[(size_t)gm*K+gk+2]; if (gk+3<K) t3=A[(size_t)gm*K+gk+3];
                   va = make_float4(t0,t1,t2,t3); }
        }
        As[kk+0][r]=va.x; As[kk+1][r]=va.y; As[kk+2][r]=va.z; As[kk+3][r]=va.w;
        float4 vw = make_float4(0,0,0,0);
        int gn = bn + r;
        if (gn < N) {
            if (gk + 3 < K) vw = *reinterpret_cast<const float4*>(W + (size_t)gn*K + gk);
            else { float t0=0,t1=0,t2=0,t3=0;
                   if (gk+0<K) t0=W[(size_t)gn*K+gk+0]; if (gk+1<K) t1=W[(size_t)gn*K+gk+1];
                   if (gk+2<K) t2=W[(size_t)gn*K+gk+2]; if (gk+3<K) t3=W[(size_t)gn*K+gk+3];
                   vw = make_float4(t0,t1,t2,t3); }
        }
        Ws[kk+0][r]=vw.x; Ws[kk+1][r]=vw.y; Ws[kk+2][r]=vw.z; Ws[kk+3][r]=vw.w;
        __syncthreads();
        #pragma unroll
        for (int k = 0; k < 16; k++) {
            float4 a = *reinterpret_cast<const float4*>(&As[k][ty*4]);
            float4 b = *reinterpret_cast<const float4*>(&Ws[k][tx*4]);
            acc[0][0]+=a.x*b.x; acc[0][1]+=a.x*b.y; acc[0][2]+=a.x*b.z; acc[0][3]+=a.x*b.w;
            acc[1][0]+=a.y*b.x; acc[1][1]+=a.y*b.y; acc[1][2]+=a.y*b.z; acc[1][3]+=a.y*b.w;
            acc[2][0]+=a.z*b.x; acc[2][1]+=a.z*b.y; acc[2][2]+=a.z*b.z; acc[2][3]+=a.z*b.w;
            acc[3][0]+=a.w*b.x; acc[3][1]+=a.w*b.y; acc[3][2]+=a.w*b.z; acc[3][3]+=a.w*b.w;
        }
        __syncthreads();
    }
    #pragma unroll
    for (int i = 0; i < 4; i++) {
        int gm = bm + ty*4 + i; if (gm >= M) continue;
        #pragma unroll
        for (int j = 0; j < 4; j++) {
            int gn = bn + tx*4 + j; if (gn >= N) continue;
            C[(size_t)gm*N + gn] = acc[i][j] + (bias ? bias[gn] : 0.f);
        }
    }
}

__global__ void gemm_splitk(const float* __restrict__ A, const float* __restrict__ W,
                            float* __restrict__ Cp, int M, int N, int K, int kchunk) {
    __shared__ float As[16][64];
    __shared__ float Ws[16][64];
    int z = blockIdx.y;
    int ks = z * kchunk;
    int ke = min(K, ks + kchunk);
    int bn = blockIdx.x * 64;
    int tid = threadIdx.x;
    int tx = tid & 15, ty = tid >> 4;
    float acc[4][4] = {};
    int r  = tid >> 2;
    int kk = (tid & 3) * 4;
    for (int k0 = ks; k0 < ke; k0 += 16) {
        int gk = k0 + kk;
        float4 va = make_float4(0,0,0,0);
        if (r < M) {
            if (gk + 3 < ke) va = *reinterpret_cast<const float4*>(A + (size_t)r*K + gk);
            else { float t0=0,t1=0,t2=0,t3=0;
                   if (gk+0<ke) t0=A[(size_t)r*K+gk+0]; if (gk+1<ke) t1=A[(size_t)r*K+gk+1];
                   if (gk+2<ke) t2=A[(size_t)r*K+gk+2]; if (gk+3<ke) t3=A[(size_t)r*K+gk+3];
                   va = make_float4(t0,t1,t2,t3); }
        }
        As[kk+0][r]=va.x; As[kk+1][r]=va.y; As[kk+2][r]=va.z; As[kk+3][r]=va.w;
        float4 vw = make_float4(0,0,0,0);
        int gn = bn + r;
        if (gn < N) {
            if (gk + 3 < ke) vw = *reinterpret_cast<const float4*>(W + (size_t)gn*K + gk);
            else { float t0=0,t1=0,t2=0,t3=0;
                   if (gk+0<ke) t0=W[(size_t)gn*K+gk+0]; if (gk+1<ke) t1=W[(size_t)gn*K+gk+1];
                   if (gk+2<ke) t2=W[(size_t)gn*K+gk+2]; if (gk+3<ke) t3=W[(size_t)gn*K+gk+3];
                   vw = make_float4(t0,t1,t2,t3); }
        }
        Ws[kk+0][r]=vw.x; Ws[kk+1][r]=vw.y; Ws[kk+2][r]=vw.z; Ws[kk+3][r]=vw.w;
        __syncthreads();
        #pragma unroll
        for (int k = 0; k < 16; k++) {
            float4 a = *reinterpret_cast<const float4*>(&As[k][ty*4]);
            float4 b = *reinterpret_cast<const float4*>(&Ws[k][tx*4]);
            acc[0][0]+=a.x*b.x; acc[0][1]+=a.x*b.y; acc[0][2]+=a.x*b.z; acc[0][3]+=a.x*b.w;
            acc[1][0]+=a.y*b.x; acc[1][1]+=a.y*b.y; acc[1][2]+=a.y*b.z; acc[1][3]+=a.y*b.w;
            acc[2][0]+=a.z*b.x; acc[2][1]+=a.z*b.y; acc[2][2]+=a.z*b.z; acc[2][3]+=a.z*b.w;
            acc[3][0]+=a.w*b.x; acc[3][1]+=a.w*b.y; acc[3][2]+=a.w*b.z; acc[3][3]+=a.w*b.w;
        }
        __syncthreads();
    }
    float* Cz = Cp + (size_t)z*M*N;
    #pragma unroll
    for (int i = 0; i < 4; i++) {
        int gm = ty*4 + i; if (gm >= M) continue;
        #pragma unroll
        for (int j = 0; j < 4; j++) {
            int gn = bn + tx*4 + j; if (gn >= N) continue;
            Cz[(size_t)gm*N + gn] = acc[i][j];
        }
    }
}

// ---------------- encoder step gates ----------------
__global__ void enc_gates(const float* __restrict__ gxe, const float* __restrict__ ghp,
                          const float* __restrict__ bhh, float* __restrict__ h,
                          float* __restrict__ po, const int* __restrict__ post_length, int t) {
    int idx = blockIdx.x*blockDim.x + threadIdx.x;
    if (idx >= B*GH) return;
    int b = idx / GH, j = idx % GH;
    const float* gx = gxe + ((size_t)b*PL + t)*G3;
    float ghr = bhh[j], ghz = bhh[GH+j], ghn = bhh[2*GH+j];
    #pragma unroll
    for (int s = 0; s < 4; s++) {
        const float* p = ghp + ((size_t)s*B + b)*G3;
        ghr += p[j]; ghz += p[GH+j]; ghn += p[2*GH+j];
    }
    float r = sigmoidf_(gx[j] + ghr);
    float z = sigmoidf_(gx[GH+j] + ghz);
    float n = tanhf(gx[2*GH+j] + r*ghn);
    float hold = h[idx];
    float hn = (1.f - z)*n + z*hold;
    bool valid = t < post_length[b];
    h[idx] = valid ? hn : hold;
    po[((size_t)b*PL + t)*GH + j] = valid ? hn : 0.f;
}

// ---------------- decoder: prev-gates + attention + misc (one block per b) ---------
__global__ void __launch_bounds__(256) dec_am(
        float* __restrict__ din2, const float* __restrict__ po,
        const float* __restrict__ cp, const float* __restrict__ gxrv_prev,
        const float* __restrict__ bhh,
        const float* __restrict__ wb_w, const float* __restrict__ wb_b,
        const float* __restrict__ wc_w, const float* __restrict__ wc_b,
        const float* __restrict__ vb_w, const float* __restrict__ vb_b,
        const float* __restrict__ ubg, const float* __restrict__ sg,
        float* __restrict__ q, float* __restrict__ da,
        float* __restrict__ Z, int t, int do_gates) {
    int b = blockIdx.x, tid = threadIdx.x;
    int lane = tid & 31, wid = tid >> 5;
    __shared__ float hs[GH];
    __shared__ float sc2[256];
    __shared__ float sc[PL];
    __shared__ float al[PL];
    __shared__ float wbh[HID];
    __shared__ float dls[NT];
    __shared__ float das[NT];
    if (do_gates) {
        #pragma unroll
        for (int jj = 0; jj < 2; jj++) {
            int j = jj*256 + tid;
            float cr = 0.f, cz = 0.f, cxn = 0.f, chn = 0.f;
            #pragma unroll
            for (int z = 0; z < 8; z++) {
                const float* p = cp + ((size_t)z*B + b)*G4;
                cr += p[j]; cz += p[512+j]; cxn += p[1024+j]; chn += p[1536+j];
            }
            const float* gr = gxrv_prev + (size_t)b*G3;
            float r  = sigmoidf_(cr + gr[j] + bhh[j]);
            float zz = sigmoidf_(cz + gr[GH+j] + bhh[GH+j]);
            float n  = tanhf(cxn + gr[2*GH+j] + r*(chn + bhh[2*GH+j]));
            float hold = din2[(size_t)b*KC + 1012 + j];
            float hn = (1.f - zz)*n + zz*hold;
            din2[(size_t)b*KC + 1012 + j] = hn;
            Z[((size_t)(t-1)*B + b)*KD + j] = hn;
            hs[j] = hn;
        }
        __syncthreads();
    } else {
        for (int i = tid; i < GH; i += 256) hs[i] = din2[(size_t)b*KC + 1012 + i];
        __syncthreads();
    }
    {   // scores: 2 threads per p
        int p = tid >> 1, hf = tid & 1;
        const float* row = po + ((size_t)b*PL + p)*GH + hf*256;
        const float* h2 = hs + hf*256;
        float s = 0.f;
        for (int k = 0; k < 256; k += 4) {
            float4 v = *reinterpret_cast<const float4*>(row + k);
            s += v.x*h2[k] + v.y*h2[k+1] + v.z*h2[k+2] + v.w*h2[k+3];
        }
        sc2[tid] = s;
    }
    __syncthreads();
    if (tid < PL) sc[tid] = sc2[2*tid] + sc2[2*tid+1];
    __syncthreads();
    // q (300) + wbh (100)
    for (int j = tid; j < 400; j += 256) {
        const float* w;
        float acc;
        if (j < 300) { acc = wc_b[j]; w = wc_w + (size_t)j*GH; }
        else         { acc = wb_b[j-300]; w = wb_w + (size_t)(j-300)*GH; }
        for (int k = 0; k < GH; k += 4) {
            float4 v = *reinterpret_cast<const float4*>(w + k);
            acc += v.x*hs[k] + v.y*hs[k+1] + v.z*hs[k+2] + v.w*hs[k+3];
        }
        if (j < 300) q[(size_t)b*300 + j] = acc;
        else wbh[j-300] = acc;
    }
    if (wid == 0) {
        float v0 = sc[lane], v1 = sc[lane+32], v2 = sc[lane+64], v3 = sc[lane+96];
        float m = fmaxf(fmaxf(v0, v1), fmaxf(v2, v3));
        for (int o = 16; o; o >>= 1) m = fmaxf(m, __shfl_xor_sync(0xffffffffu, m, o));
        float e0 = expf(v0-m), e1 = expf(v1-m), e2 = expf(v2-m), e3 = expf(v3-m);
        float s = e0+e1+e2+e3;
        for (int o = 16; o; o >>= 1) s += __shfl_xor_sync(0xffffffffu, s, o);
        float inv = 1.f/s;
        al[lane] = e0*inv; al[lane+32] = e1*inv; al[lane+64] = e2*inv; al[lane+96] = e3*inv;
    }
    __syncthreads();
    for (int d = tid; d < GH; d += 256) {
        float acc = 0.f;
        for (int p = 0; p < PL; p++) acc += al[p]*po[((size_t)b*PL + p)*GH + d];
        din2[(size_t)b*KC + d] = acc;
    }
    if (tid < NT) {
        float s = 0.f;
        const float* u = ubg + ((size_t)b*NT + tid)*HID;
        for (int j = 0; j < HID; j++) s += vb_w[j]*tanhf(wbh[j] + u[j]);
        dls[tid] = s + vb_b[0];
    }
    __syncthreads();
    if (wid == 0) {
        float a0 = (lane < NT) ? dls[lane] : -1e30f;
        float a1 = (lane+32 < NT) ? dls[lane+32] : -1e30f;
        float m = fmaxf(a0, a1);
        for (int o = 16; o; o >>= 1) m = fmaxf(m, __shfl_xor_sync(0xffffffffu, m, o));
        float e0 = (lane < NT) ? expf(a0-m) : 0.f;
        float e1 = (lane+32 < NT) ? expf(a1-m) : 0.f;
        float s = e0 + e1;
        for (int o = 16; o; o >>= 1) s += __shfl_xor_sync(0xffffffffu, s, o);
        float inv = 1.f/s;
        if (lane < NT)    { das[lane] = e0*inv;    da[(size_t)b*NT + lane] = e0*inv; }
        if (lane+32 < NT) { das[lane+32] = e1*inv; da[(size_t)b*NT + lane+32] = e1*inv; }
    }
    __syncthreads();
    float* zrow = Z + ((size_t)t*B + b)*KD;
    for (int d = tid; d < 200; d += 256) {
        float s = 0.f;
        for (int n = 0; n < NT; n++) s += das[n]*sg[((size_t)b*NT + n)*200 + d];
        din2[(size_t)b*KC + 512 + d] = s;
        zrow[512 + d] = s;
    }
}

// ---------------- triple attention: partial over n-chunks, fp16 tef ----------------
__global__ void __launch_bounds__(256) dec_tv_part(
        const __half* __restrict__ tef16, const float* __restrict__ q,
        const float* __restrict__ da, float* __restrict__ tvp) {
    int b = blockIdx.x, ch = blockIdx.y;
    int tid = threadIdx.x, lane = tid & 31, wid = tid >> 5;
    __shared__ float qs[300];
    __shared__ float sw[10*NP];
    __shared__ float dal[10];
    for (int i = tid; i < 300; i += 256) qs[i] = q[(size_t)b*300 + i];
    if (tid < 10) dal[tid] = da[(size_t)b*NT + ch*10 + tid];
    __syncthreads();
    const __half* tb = tef16 + ((size_t)b*NT + ch*10)*NP*300;
    // pass 1: scores (half2 loads, fp32 accum)
    #pragma unroll
    for (int it = 0; it < 25; it++) {
        int pair = wid + 8*it;
        const __half* row = tb + (size_t)pair*300;
        float s = 0.f;
        for (int k2 = lane; k2 < 150; k2 += 32) {
            __half2 hv = *reinterpret_cast<const __half2*>(row + 2*k2);
            float2 fv = __half22float2(hv);
            s += fv.x*qs[2*k2] + fv.y*qs[2*k2+1];
        }
        #pragma unroll
        for (int o = 16; o; o >>= 1) s += __shfl_down_sync(0xffffffffu, s, o);
        if (lane == 0) sw[pair] = s;
    }
    __syncthreads();
    for (int n = wid; n < 10; n += 8) {
        float v = (lane < NP) ? sw[n*NP + lane] : -1e30f;
        float m = v;
        for (int o = 16; o; o >>= 1) m = fmaxf(m, __shfl_xor_sync(0xffffffffu, m, o));
        float e = (lane < NP) ? expf(v - m) : 0.f;
        float su = e;
        for (int o = 16; o; o >>= 1) su += __shfl_xor_sync(0xffffffffu, su, o);
        if (lane < NP) sw[n*NP + lane] = e * dal[n] / su;
    }
    __syncthreads();
    // pass 2: weighted accumulation (fp16 loads L2-hot, fp32 accum)
    for (int d = tid; d < 300; d += 256) {
        float acc = 0.f;
        #pragma unroll 8
        for (int r = 0; r < 200; r++) acc += sw[r]*__half2float(tb[(size_t)r*300 + d]);
        tvp[((size_t)b*NCH + ch)*300 + d] = acc;
    }
}

__global__ void dec_tvsum(const float* __restrict__ tvp, float* __restrict__ din2,
                          float* __restrict__ Z, int t) {
    int b = blockIdx.x, d = threadIdx.x;
    float s = 0.f;
    #pragma unroll
    for (int ch = 0; ch < NCH; ch++) s += tvp[((size_t)b*NCH + ch)*300 + d];
    din2[(size_t)b*KC + 712 + d] = s;
    Z[((size_t)t*B + b)*KD + 712 + d] = s;
}

// final gates for last decoder step
__global__ void dec_gates2(const float* __restrict__ cp, const float* __restrict__ gxrv_t,
                           const float* __restrict__ bhh, float* __restrict__ din2,
                           float* __restrict__ Z, int t) {
    int idx = blockIdx.x*blockDim.x + threadIdx.x;
    if (idx >= B*GH) return;
    int b = idx / GH, j = idx % GH;
    float cr = 0.f, cz = 0.f, cxn = 0.f, chn = 0.f;
    #pragma unroll
    for (int z = 0; z < 8; z++) {
        const float* p = cp + ((size_t)z*B + b)*G4;
        cr += p[j]; cz += p[512+j]; cxn += p[1024+j]; chn += p[1536+j];
    }
    const float* gr = gxrv_t + (size_t)b*G3;
    float r  = sigmoidf_(cr + gr[j] + bhh[j]);
    float zz = sigmoidf_(cz + gr[GH+j] + bhh[GH+j]);
    float n  = tanhf(cxn + gr[2*GH+j] + r*(chn + bhh[2*GH+j]));
    float hold = din2[(size_t)b*KC + 1012 + j];
    float hn = (1.f - zz)*n + zz*hold;
    din2[(size_t)b*KC + 1012 + j] = hn;
    Z[((size_t)t*B + b)*KD + j] = hn;
}

// ---------------- fp16 2-term split prep ----------------
__global__ void k_split_W(const float* __restrict__ W, __half* __restrict__ Ws) {
    size_t i = (size_t)blockIdx.x*blockDim.x + threadIdx.x;
    size_t total = (size_t)VW*(KP/8);
    if (i >= total) return;
    int cg = (int)(i % (KP/8));
    size_t r = i / (KP/8);
    int c0 = cg*8;
    __half o[8];
    #pragma unroll
    for (int e = 0; e < 8; e++) {
        int c = c0 + e;
        __half v = __float2half(0.f);
        if (c < 2*KSEG) {
            int kc = (c < KSEG) ? c : c - KSEG;
            v = __float2half(W[r*KSEG + kc]);
        }
        o[e] = v;
    }
    *reinterpret_cast<uint4*>(Ws + r*KP + c0) = *reinterpret_cast<uint4*>(o);
}

__global__ void k_split_Z(const float* __restrict__ Z, __half* __restrict__ As_) {
    size_t i = (size_t)blockIdx.x*blockDim.x + threadIdx.x;
    size_t total = (size_t)MP*(KP/8);
    if (i >= total) return;
    int cg = (int)(i % (KP/8));
    int m = (int)(i / (KP/8));
    int b = m / TDEC, t = m - b*TDEC;
    int c0 = cg*8;
    __half o[8];
    #pragma unroll
    for (int e = 0; e < 8; e++) {
        int c = c0 + e;
        __half v = __float2half(0.f);
        if (b < B && c < 2*KSEG) {
            int kc = (c < KSEG) ? c : c - KSEG;
            float z = Z[((size_t)t*B + b)*KD + kc];
            __half hh = __float2half(z);
            if (c >= KSEG) v = __float2half(z - __half2float(hh));
            else v = hh;
        }
        o[e] = v;
    }
    *reinterpret_cast<uint4*>(As_ + (size_t)m*KP + c0) = *reinterpret_cast<uint4*>(o);
}

// ---------------- mma.sync fp16 vocab GEMM: 256x128 CTA tile, 3-stage ----------------
__global__ void __launch_bounds__(256) vocab_mma(
        const __half* __restrict__ Ag, const __half* __restrict__ Wg,
        const float* __restrict__ bout, float* __restrict__ out) {
    extern __shared__ __align__(16) char sraw[];
    const int tid = threadIdx.x;
    const int wid = tid >> 5, lane = tid & 31;
    const int m0 = blockIdx.x * VTM, n0 = blockIdx.y * VTN;
    const int wm = (wid >> 1) * 64, wn = (wid & 1) * 64;
    const int g = lane >> 2, tg = lane & 3;
    const uint32_t sb = smem_u32(sraw);

    float acc[4][8][4];
    #pragma unroll
    for (int i = 0; i < 4; i++)
    #pragma unroll
    for (int j = 0; j < 8; j++) { acc[i][j][0]=0.f; acc[i][j][1]=0.f; acc[i][j][2]=0.f; acc[i][j][3]=0.f; }

    auto load_stage = [&](int s, int k0) {
        uint32_t base = sb + (uint32_t)s*VSTAGE;
        #pragma unroll
        for (int i = 0; i < 6; i++) {
            int c = i*256 + tid;
            int isB = (c >= 1024);
            int cc = isB ? (c - 1024) : c;
            int row = cc >> 2, ch = cc & 3;
            uint32_t dst = base + (isB ? VSTAGE_A : 0u)
                         + (uint32_t)row*(SSTRIDE*2) + (uint32_t)ch*16u;
            const __half* src = isB ? (Wg + (size_t)(n0+row)*KP + k0 + ch*8)
                                    : (Ag + (size_t)(m0+row)*KP + k0 + ch*8);
            asm volatile("cp.async.cg.shared.global [%0], [%1], 16;" :: "r"(dst), "l"(src));
        }
        asm volatile("cp.async.commit_group;" ::: "memory");
    };

    load_stage(0, 0); load_stage(1, 32); load_stage(2, 64);

    const int a_row = lane & 15;
    const int a_k8  = (lane >> 4) << 3;
    const int b_row = lane & 7;
    const int b_k8  = ((lane >> 3) & 1) << 3;
    const int b_ni  = lane >> 4;           // 0/1: which ni of the x4 pair

    const int NIT = KP/32;                 // 102
    for (int kt = 0; kt < NIT; kt++) {
        if (kt + 3 < NIT) { asm volatile("cp.async.wait_group 2;" ::: "memory"); }
        else              { asm volatile("cp.async.wait_group 0;" ::: "memory"); }
        __syncthreads();
        int s = kt % 3;
        uint32_t baseA = sb + (uint32_t)s*VSTAGE;
        uint32_t baseB = baseA + VSTAGE_A;
        #pragma unroll
        for (int kk = 0; kk < 2; kk++) {
            uint32_t afr[4][4];
            #pragma unroll
            for (int mi = 0; mi < 4; mi++) {
                uint32_t ad = baseA + ((uint32_t)(wm + mi*16 + a_row)*SSTRIDE
                                       + (uint32_t)(kk*16 + a_k8))*2u;
                asm volatile("ldmatrix.sync.aligned.m8n8.x4.shared.b16 {%0,%1,%2,%3}, [%4];"
                    : "=r"(afr[mi][0]),"=r"(afr[mi][1]),"=r"(afr[mi][2]),"=r"(afr[mi][3])
                    : "r"(ad));
            }
            uint32_t bfr[8][2];
            #pragma unroll
            for (int ni = 0; ni < 8; ni += 2) {
                uint32_t bd = baseB + ((uint32_t)(wn + (ni + b_ni)*8 + b_row)*SSTRIDE
                                       + (uint32_t)(kk*16 + b_k8))*2u;
                asm volatile("ldmatrix.sync.aligned.m8n8.x4.shared.b16 {%0,%1,%2,%3}, [%4];"
                    : "=r"(bfr[ni][0]),"=r"(bfr[ni][1]),"=r"(bfr[ni+1][0]),"=r"(bfr[ni+1][1])
                    : "r"(bd));
            }
            #pragma unroll
            for (int mi = 0; mi < 4; mi++)
            #pragma unroll
            for (int ni = 0; ni < 8; ni++) {
                asm volatile(
                  "mma.sync.aligned.m16n8k16.row.col.f32.f16.f16.f32 "
                  "{%0,%1,%2,%3},{%4,%5,%6,%7},{%8,%9},{%0,%1,%2,%3};"
                  : "+f"(acc[mi][ni][0]), "+f"(acc[mi][ni][1]),
                    "+f"(acc[mi][ni][2]), "+f"(acc[mi][ni][3])
                  : "r"(afr[mi][0]),"r"(afr[mi][1]),"r"(afr[mi][2]),"r"(afr[mi][3]),
                    "r"(bfr[ni][0]),"r"(bfr[ni][1]));
            }
        }
        __syncthreads();
        if (kt + 3 < NIT) load_stage(s, (kt+3)*32);
    }
    __syncthreads();

    float* Ds = (float*)sraw;
    #pragma unroll
    for (int h = 0; h < 2; h++) {
        if ((wid >> 2) == h) {
            int mbase = wm - h*128;
            #pragma unroll
            for (int mi = 0; mi < 4; mi++) {
                int mA = mbase + mi*16 + g;
                #pragma unroll
                for (int ni = 0; ni < 8; ni++) {
                    int nn = wn + ni*8 + tg*2;
                    Ds[mA*129 + nn]         = acc[mi][ni][0];
                    Ds[mA*129 + nn + 1]     = acc[mi][ni][1];
                    Ds[(mA+8)*129 + nn]     = acc[mi][ni][2];
                    Ds[(mA+8)*129 + nn + 1] = acc[mi][ni][3];
                }
            }
        }
        __syncthreads();
        for (int idx = tid; idx < VTN*128; idx += 256) {
            int n = idx >> 7, m = idx & 127;
            int mg = m0 + h*128 + m;
            if (mg < B*TDEC) {
                int bb = mg / TDEC, tt = mg - bb*TDEC;
                int ng = n0 + n;
                out[(size_t)bb*VW*TDEC + (size_t)ng*TDEC + tt] = Ds[m*129 + n] + __ldg(bout + ng);
            }
        }
        __syncthreads();
    }
}

// ---------------- launch ----------------
extern "C" void kernel_launch(void* const* d_in, const int* in_sizes, int n_in,
                              void* d_out, int out_size) {
    const float* word_emb   = (const float*)d_in[0];
    const float* transe_emb = (const float*)d_in[1];
    const float* wh_w = (const float*)d_in[2];  const float* wh_b = (const float*)d_in[3];
    const float* wr_w = (const float*)d_in[4];  const float* wr_b = (const float*)d_in[5];
    const float* wt_w = (const float*)d_in[6];  const float* wt_b = (const float*)d_in[7];
    const float* wb_w = (const float*)d_in[8];  const float* wb_b = (const float*)d_in[9];
    const float* ub_w = (const float*)d_in[10]; const float* ub_b = (const float*)d_in[11];
    const float* vb_w = (const float*)d_in[12]; const float* vb_b = (const float*)d_in[13];
    const float* wc_w = (const float*)d_in[14]; const float* wc_b = (const float*)d_in[15];
    const float* Wih_e = (const float*)d_in[16]; const float* Whh_e = (const float*)d_in[17];
    const float* bih_e = (const float*)d_in[18]; const float* bhh_e = (const float*)d_in[19];
    const float* Wih_d = (const float*)d_in[20]; const float* Whh_d = (const float*)d_in[21];
    const float* bih_d = (const float*)d_in[22]; const float* bhh_d = (const float*)d_in[23];
    const float* out_w = (const float*)d_in[24]; const float* out_b = (const float*)d_in[25];
    const int* post          = (const int*)d_in[26];
    const int* post_length   = (const int*)d_in[27];
    const int* response      = (const int*)d_in[28];
    const int* resp_triple   = (const int*)d_in[29];
    const int* post_triple   = (const int*)d_in[30];
    const int* triple        = (const int*)d_in[31];
    float* out = (float*)d_out;

    void* basep = nullptr; cudaGetSymbolAddress(&basep, g_buf);
    float* base = (float*)basep;
    void* wsp = nullptr; cudaGetSymbolAddress(&wsp, g_Ws);
    void* asp = nullptr; cudaGetSymbolAddress(&asp, g_As);
    void* t16p = nullptr; cudaGetSymbolAddress(&t16p, g_tef16);
    __half* Ws = (__half*)wsp;
    __half* As = (__half*)asp;
    __half* tef16 = (__half*)t16p;

    float* tef  = base + OFF_TEF;
    float* sl   = base + OFF_SL;
    float* sg   = base + OFF_SG;
    float* ubg  = base + OFF_UBG;
    float* pin  = base + OFF_PIN;
    float* gxe  = base + OFF_GXE;
    float* po   = base + OFF_PO;
    float* h    = base + OFF_H;
    float* rv   = base + OFF_RV;
    float* Z    = base + OFF_Z;
    float* din2 = base + OFF_DIN2;
    float* q    = base + OFF_Q;
    float* da   = base + OFF_DA;
    float* cp   = base + OFF_CP;
    float* ghp  = base + OFF_GHP;
    float* gxrv = base + OFF_GXRV;
    float* Wcb  = base + OFF_WCB;
    float* Wrv  = base + OFF_WRV;
    float* tvp  = base + OFF_TVP;

    cudaFuncSetAttribute(vocab_mma, cudaFuncAttributeMaxDynamicSharedMemorySize, VSMEM);

    // ---- phase A ----
    k_zero<<<(unsigned)((SZ_H + 255)/256), 256>>>(h, SZ_H);
    {
        size_t n4 = (size_t)B*NT*NP*3*25;
        k_gather_tef<<<(unsigned)((n4 + 255)/256), 256>>>(transe_emb, triple, tef, tef16);
    }
    {
        size_t n4 = (size_t)TDEC*B*150;
        k_gather_rv<<<(unsigned)((n4 + 255)/256), 256>>>(word_emb, transe_emb, response, resp_triple, rv, Z);
    }
    {
        size_t nsp = (size_t)VW*(KP/8);
        k_split_W<<<(unsigned)((nsp + 255)/256), 256>>>(out_w, Ws);
    }
    {
        size_t n = (size_t)G4*KC;
        k_build_wcomb<<<(unsigned)((n + 255)/256), 256>>>(Wih_d, Whh_d, Wcb);
    }
    {
        size_t n = (size_t)G3*600;
        k_build_wrv<<<(unsigned)((n + 255)/256), 256>>>(Wih_d, Wrv);
    }
    k_triple_score<<<B*NT*NP, 128>>>(tef, triple, wh_w, wh_b, wr_w, wr_b, wt_w, wt_b, sl);
    k_graph_softmax<<<B*NT, 64>>>(sl, tef, sg);
    k_ubg<<<B*NT, 128>>>(sg, ub_w, ub_b, ubg);
    {
        size_t n4 = (size_t)B*PL*125;
        k_post_in<<<(unsigned)((n4 + 255)/256), 256>>>(word_emb, sg, post, post_triple, pin);
    }
    gemm_bias<<<dim3((B*PL)/64, G3/64), 256>>>(pin, Wih_e, bih_e, gxe, B*PL, G3, KE);
    gemm_bias<<<dim3((TDEC*B)/64, G3/64), 256>>>(rv, Wrv, bih_d, gxrv, TDEC*B, G3, 600);

    // ---- phase B: encoder recurrence ----
    for (int t = 0; t < PL; t++) {
        gemm_splitk<<<dim3(G3/64, 4), 256>>>(h, Whh_e, ghp, B, G3, GH, 128);
        enc_gates<<<(B*GH)/256, 256>>>(gxe, ghp, bhh_e, h, po, post_length, t);
    }
    k_h2din2<<<(B*GH)/256, 256>>>(h, din2);

    // ---- phase C: decoder recurrence (4 launches/step) ----
    for (int t = 0; t < TDEC; t++) {
        const float* gxrv_prev = (t > 0) ? (gxrv + (size_t)(t-1)*B*G3) : gxrv;
        dec_am<<<B, 256>>>(din2, po, cp, gxrv_prev, bhh_d,
                           wb_w, wb_b, wc_w, wc_b, vb_w, vb_b,
                           ubg, sg, q, da, Z, t, t > 0 ? 1 : 0);
        dec_tv_part<<<dim3(B, NCH), 256>>>(tef16, q, da, tvp);
        dec_tvsum<<<B, 300>>>(tvp, din2, Z, t);
        gemm_splitk<<<dim3(G4/64, 8), 256>>>(din2, Wcb, cp, B, G4, KC, 192);
    }
    dec_gates2<<<(B*GH)/256, 256>>>(cp, gxrv + (size_t)(TDEC-1)*B*G3, bhh_d, din2, Z, TDEC-1);

    // ---- phase D: split Z + vocab projection ----
    {
        size_t nsp = (size_t)MP*(KP/8);
        k_split_Z<<<(unsigned)((nsp + 255)/256), 256>>>(Z, As);
    }
    vocab_mma<<<dim3(MP/VTM, VW/VTN), 256, VSMEM>>>(As, Ws, out_b, out);
}